// round 1
// baseline (speedup 1.0000x reference)
#include <cuda_runtime.h>
#include <math.h>

// Problem constants
constexpr int B_  = 32;
constexpr int T_  = 512;
constexpr int D_  = 512;
constexpr int H_  = 8;
constexpr int DH_ = 64;
constexpr int HB_ = H_ * B_;        // 256
constexpr int FF_ = 4 * D_;         // 2048

// ---------------- scratch (static device globals; allocation-free) ----------
__device__ float g_pe[T_ * D_];                    // [T,D]
__device__ float g_q1[B_ * T_ * D_];               // pos-encoded queries
__device__ float g_k1[B_ * T_ * D_];               // pos-encoded twice
__device__ float g_Q [B_ * T_ * D_];
__device__ float g_K [B_ * T_ * D_];
__device__ float g_V [B_ * T_ * D_];
__device__ float g_S [(long)HB_ * T_ * T_];        // scores / attn, 256MB
__device__ float g_cmax[HB_ * T_];                 // column max over q
__device__ float g_R [B_ * T_ * D_];               // attn out + residual
__device__ float g_hidden[(long)B_ * T_ * FF_];    // FFN hidden, 128MB

// ---------------- positional encoding (fp64 to match numpy) -----------------
__global__ void pe_kernel(float* __restrict__ pe) {
    int idx = blockIdx.x * blockDim.x + threadIdx.x;     // T*D threads
    if (idx >= T_ * D_) return;
    int t = idx / D_;
    int d = idx % D_;
    double ang = (double)t * exp(-(2.0 * (double)d / (double)D_) * log(10000.0));
    double v = (d & 1) ? cos(ang) : sin(ang);
    pe[idx] = (float)(v * sqrt((double)D_));
}

__global__ void addpe_kernel(const float* __restrict__ q,
                             const float* __restrict__ pe,
                             float* __restrict__ q1, float* __restrict__ k1) {
    long idx = (long)blockIdx.x * blockDim.x + threadIdx.x;  // B*T*D
    long td = idx % ((long)T_ * D_);
    float p = pe[td];
    float a = q[idx] + p;   // q1 = queries + pe
    q1[idx] = a;
    k1[idx] = a + p;        // k1 = q1 + pe  (source bug kept)
}

// ---------------- generic batched SGEMM  C = alpha*A@B(^T) [+Res][relu] -----
// Tile 128x64x16, 256 threads, 8x4 per-thread microtile.
constexpr int BM = 128, BN = 64, BK = 16;

template<bool TB>
__global__ __launch_bounds__(256) void gemm_k(
    const float* __restrict__ A, long sA1, long sA2, int lda,
    const float* __restrict__ Bm, long sB1, long sB2, int ldb,
    float* __restrict__ C, long sC1, long sC2, int ldc,
    const float* __restrict__ Res, long sR1, long sR2, int ldres,
    int nb2, int K, float alpha, int relu)
{
    __shared__ float As[BK][BM + 4];   // row pitch 132 floats (16B-aligned rows)
    __shared__ float Bs[BK][BN + 4];   // row pitch 68 floats

    int z  = blockIdx.z;
    int i1 = z / nb2, i2 = z % nb2;
    A  += i1 * sA1 + i2 * sA2;
    Bm += i1 * sB1 + i2 * sB2;
    C  += i1 * sC1 + i2 * sC2;
    if (Res) Res += i1 * sR1 + i2 * sR2;

    int tid = threadIdx.x;
    int tx = tid % 16;     // N direction (16*4 = 64)
    int ty = tid / 16;     // M direction (16*8 = 128)
    int row0 = blockIdx.y * BM;
    int col0 = blockIdx.x * BN;

    float acc[8][4];
    #pragma unroll
    for (int i = 0; i < 8; i++)
        #pragma unroll
        for (int j = 0; j < 4; j++) acc[i][j] = 0.f;

    for (int k0 = 0; k0 < K; k0 += BK) {
        // load A tile: 128x16
        #pragma unroll
        for (int l = 0; l < 8; l++) {
            int idx = tid + l * 256;
            int c = idx % BK;
            int r = idx / BK;
            As[c][r] = A[(long)(row0 + r) * lda + (k0 + c)];
        }
        // load B tile: 16x64
        if (!TB) {
            #pragma unroll
            for (int l = 0; l < 4; l++) {
                int idx = tid + l * 256;
                int n = idx % BN;
                int c = idx / BN;
                Bs[c][n] = Bm[(long)(k0 + c) * ldb + (col0 + n)];
            }
        } else {
            #pragma unroll
            for (int l = 0; l < 4; l++) {
                int idx = tid + l * 256;
                int c = idx % BK;
                int n = idx / BK;
                Bs[c][n] = Bm[(long)(col0 + n) * ldb + (k0 + c)];
            }
        }
        __syncthreads();

        #pragma unroll
        for (int kk = 0; kk < BK; kk++) {
            float4 a0 = *(const float4*)&As[kk][ty * 8];
            float4 a1 = *(const float4*)&As[kk][ty * 8 + 4];
            float4 b0 = *(const float4*)&Bs[kk][tx * 4];
            float a[8] = {a0.x, a0.y, a0.z, a0.w, a1.x, a1.y, a1.z, a1.w};
            float b[4] = {b0.x, b0.y, b0.z, b0.w};
            #pragma unroll
            for (int i = 0; i < 8; i++)
                #pragma unroll
                for (int j = 0; j < 4; j++)
                    acc[i][j] = fmaf(a[i], b[j], acc[i][j]);
        }
        __syncthreads();
    }

    #pragma unroll
    for (int i = 0; i < 8; i++) {
        long r = row0 + ty * 8 + i;
        #pragma unroll
        for (int j = 0; j < 4; j++) {
            long c = col0 + tx * 4 + j;
            float v = acc[i][j] * alpha;
            if (Res)  v += Res[r * (long)ldres + c];
            if (relu) v = fmaxf(v, 0.f);
            C[r * (long)ldc + c] = v;
        }
    }
}

// ---------------- column max over q (per (hb, k)) ---------------------------
__global__ __launch_bounds__(256) void colmax_kernel(const float* __restrict__ S,
                                                     float* __restrict__ cmax) {
    int k = blockIdx.x * blockDim.x + threadIdx.x;   // 0..T-1
    int z = blockIdx.y;                              // 0..HB-1
    const float* Sp = S + (long)z * T_ * T_ + k;
    float m = -INFINITY;
    #pragma unroll 4
    for (int q = 0; q < T_; q++) m = fmaxf(m, Sp[(long)q * T_]);
    cmax[(long)z * T_ + k] = m;
}

// ---------------- row softmax of (s - colmax), times qmask ------------------
__global__ __launch_bounds__(256) void softmax_kernel(float* __restrict__ S,
                                                      const float* __restrict__ cmax,
                                                      const int* __restrict__ qmasks) {
    __shared__ float sh[8];
    __shared__ float bc;
    int q = blockIdx.x;
    int z = blockIdx.y;          // z = h*B + b
    int b = z % B_;
    float* row = S + (long)z * T_ * T_ + (long)q * T_;
    const float* cm = cmax + (long)z * T_;
    int tid = threadIdx.x;

    float x0 = row[tid]       - cm[tid];
    float x1 = row[tid + 256] - cm[tid + 256];

    // block max (jax softmax subtracts its own row max internally)
    float v = fmaxf(x0, x1);
    #pragma unroll
    for (int o = 16; o; o >>= 1) v = fmaxf(v, __shfl_xor_sync(0xffffffffu, v, o));
    if ((tid & 31) == 0) sh[tid >> 5] = v;
    __syncthreads();
    if (tid == 0) {
        float m = sh[0];
        #pragma unroll
        for (int i = 1; i < 8; i++) m = fmaxf(m, sh[i]);
        bc = m;
    }
    __syncthreads();
    float m = bc;

    float e0 = expf(x0 - m), e1 = expf(x1 - m);
    v = e0 + e1;
    #pragma unroll
    for (int o = 16; o; o >>= 1) v += __shfl_xor_sync(0xffffffffu, v, o);
    __syncthreads();
    if ((tid & 31) == 0) sh[tid >> 5] = v;
    __syncthreads();
    if (tid == 0) {
        float s = 0.f;
        #pragma unroll
        for (int i = 0; i < 8; i++) s += sh[i];
        bc = s;
    }
    __syncthreads();

    float qm  = (q < qmasks[b]) ? 1.f : 0.f;   // mask applied AFTER normalize
    float inv = qm / bc;
    row[tid]       = e0 * inv;
    row[tid + 256] = e1 * inv;
}

// ---------------- launch --------------------------------------------------
extern "C" void kernel_launch(void* const* d_in, const int* in_sizes, int n_in,
                              void* d_out, int out_size) {
    const float* queries = (const float*)d_in[0];
    // d_in[1] = keys (unused, source bug kept)
    const int*   qmasks  = (const int*)d_in[2];
    // d_in[3] = key_masks (unused by reference)
    const float* W_Q = (const float*)d_in[4];
    const float* W_K = (const float*)d_in[5];
    const float* W_V = (const float*)d_in[6];
    const float* fw1 = (const float*)d_in[7];
    const float* fw2 = (const float*)d_in[8];
    float* out = (float*)d_out;

    float *pe, *q1, *k1, *Q, *Kp, *V, *S, *cmax, *R, *hidden;
    cudaGetSymbolAddress((void**)&pe, g_pe);
    cudaGetSymbolAddress((void**)&q1, g_q1);
    cudaGetSymbolAddress((void**)&k1, g_k1);
    cudaGetSymbolAddress((void**)&Q,  g_Q);
    cudaGetSymbolAddress((void**)&Kp, g_K);
    cudaGetSymbolAddress((void**)&V,  g_V);
    cudaGetSymbolAddress((void**)&S,  g_S);
    cudaGetSymbolAddress((void**)&cmax, g_cmax);
    cudaGetSymbolAddress((void**)&R,  g_R);
    cudaGetSymbolAddress((void**)&hidden, g_hidden);

    const long TD  = (long)T_ * D_;
    const long TT  = (long)T_ * T_;

    // 1) posenc
    pe_kernel<<<(T_ * D_ + 255) / 256, 256>>>(pe);
    addpe_kernel<<<(B_ * T_ * D_) / 256, 256>>>(queries, pe, q1, k1);

    // 2) projections: [16384,512] @ [512,512]
    {
        dim3 g(D_ / BN, (B_ * T_) / BM, 1);
        gemm_k<false><<<g, 256>>>(q1, 0, 0, D_, W_Q, 0, 0, D_, Q, 0, 0, D_,
                                  nullptr, 0, 0, 0, 1, D_, 1.f, 0);
        gemm_k<false><<<g, 256>>>(k1, 0, 0, D_, W_K, 0, 0, D_, Kp, 0, 0, D_,
                                  nullptr, 0, 0, 0, 1, D_, 1.f, 0);
        gemm_k<false><<<g, 256>>>(Kp, 0, 0, D_, W_V, 0, 0, D_, V, 0, 0, D_,
                                  nullptr, 0, 0, 0, 1, D_, 1.f, 0);   // V from projected K (bug kept)
    }

    // 3) scores: per z=h*B+b: S[z] = Qh @ Kh^T / 8
    {
        dim3 g(T_ / BN, T_ / BM, HB_);
        gemm_k<true><<<g, 256>>>(Q,  DH_, TD, D_,
                                 Kp, DH_, TD, D_,
                                 S,  (long)B_ * TT, TT, T_,
                                 nullptr, 0, 0, 0,
                                 B_, DH_, 0.125f, 0);
    }

    // 4) column max over q
    {
        dim3 g(T_ / 256, HB_);
        colmax_kernel<<<g, 256>>>(S, cmax);
    }

    // 5) softmax(s - colmax) over k, * qmask  (in place)
    {
        dim3 g(T_, HB_);
        softmax_kernel<<<g, 256>>>(S, cmax, qmasks);
    }

    // 6) out = attn @ Vh, scattered into R[b,t,h*64+:] with residual q1
    {
        dim3 g(DH_ / BN, T_ / BM, HB_);
        gemm_k<false><<<g, 256>>>(S, (long)B_ * TT, TT, T_,
                                  V, DH_, TD, D_,
                                  R, DH_, TD, D_,
                                  q1, DH_, TD, D_,
                                  B_, T_, 1.f, 0);
    }

    // 7) FFN1: hidden = relu(R @ fw1)   [16384,512]@[512,2048]
    {
        dim3 g(FF_ / BN, (B_ * T_) / BM, 1);
        gemm_k<false><<<g, 256>>>(R, 0, 0, D_, fw1, 0, 0, FF_, hidden, 0, 0, FF_,
                                  nullptr, 0, 0, 0, 1, D_, 1.f, 1);
    }

    // 8) FFN2: out = R + hidden @ fw2   [16384,2048]@[2048,512]
    {
        dim3 g(D_ / BN, (B_ * T_) / BM, 1);
        gemm_k<false><<<g, 256>>>(hidden, 0, 0, FF_, fw2, 0, 0, D_, out, 0, 0, D_,
                                  R, 0, 0, D_, 1, FF_, 1.f, 0);
    }
}

// round 3
// speedup vs baseline: 1.6877x; 1.6877x over previous
#include <cuda_runtime.h>
#include <math.h>
#include <stdint.h>

// Problem constants
constexpr int B_  = 32;
constexpr int T_  = 512;
constexpr int D_  = 512;
constexpr int H_  = 8;
constexpr int DH_ = 64;
constexpr int HB_ = H_ * B_;        // 256
constexpr int FF_ = 4 * D_;         // 2048

// ---------------- scratch (static device globals; allocation-free) ----------
__device__ float g_pe[T_ * D_];
__device__ float g_q1[B_ * T_ * D_];
__device__ float g_k1[B_ * T_ * D_];
__device__ float g_Q [B_ * T_ * D_];
__device__ float g_K [B_ * T_ * D_];
__device__ float g_V [B_ * T_ * D_];
__device__ float g_S [(long)HB_ * T_ * T_];        // 256MB
__device__ float g_cmax[HB_ * T_];
__device__ float g_R [B_ * T_ * D_];
__device__ float g_hidden[(long)B_ * T_ * FF_];    // 128MB

// ---------------- helpers ---------------------------------------------------
__device__ __forceinline__ uint32_t f2tf32(float f) {
    uint32_t u;
    asm("cvt.rna.tf32.f32 %0, %1;" : "=r"(u) : "f"(f));
    return u;
}
__device__ __forceinline__ void mma16n8k8(float* c, const uint32_t* a, const uint32_t* b) {
    asm volatile(
        "mma.sync.aligned.m16n8k8.row.col.f32.tf32.tf32.f32 "
        "{%0,%1,%2,%3}, {%4,%5,%6,%7}, {%8,%9}, {%0,%1,%2,%3};"
        : "+f"(c[0]), "+f"(c[1]), "+f"(c[2]), "+f"(c[3])
        : "r"(a[0]), "r"(a[1]), "r"(a[2]), "r"(a[3]), "r"(b[0]), "r"(b[1]));
}

// ============ tf32 mma.sync GEMM: C[M,BN-tile] = A[M,K] @ B[K,N] ============
// A row-major (lda), B row-major K x N (ldb). Optional residual + relu.
// Block tile 128 x BN, BK=16, 256 threads (8 warps).
template<int BN>
__global__ __launch_bounds__(256) void mma_gemm(
    const float* __restrict__ A, long sA1, long sA2, int lda,
    const float* __restrict__ Bm, long sB1, long sB2, int ldb,
    float* __restrict__ C, long sC1, long sC2, int ldc,
    const float* __restrict__ Res, long sR1, long sR2, int ldres,
    int nb2, int K, int relu)
{
    constexpr int nWN = (BN == 128) ? 4 : 2;
    constexpr int nWM = 8 / nWN;
    constexpr int WM  = 128 / nWM;       // warp rows
    constexpr int WN  = BN / nWN;        // warp cols
    constexpr int MT  = WM / 16;         // mma tiles per warp (M)
    constexpr int NT  = WN / 8;          // mma tiles per warp (N)
    constexpr int BP  = BN + 8;          // B smem pitch (bank-conflict-free frags)
    constexpr int BLD = BN / 16;         // B floats per thread per tile (8 or 4)

    __shared__ uint32_t As[2][128][20];  // A tile, tf32 bits, pitch 20
    __shared__ uint32_t Bs[2][16][BP];   // B tile, tf32 bits

    int z  = blockIdx.z;
    int i1 = z / nb2, i2 = z % nb2;
    A  += i1 * sA1 + i2 * sA2;
    Bm += i1 * sB1 + i2 * sB2;
    C  += i1 * sC1 + i2 * sC2;
    if (Res) Res += i1 * sR1 + i2 * sR2;

    const int tid  = threadIdx.x;
    const int lane = tid & 31;
    const int wid  = tid >> 5;
    const int warp_m = wid % nWM;
    const int warp_n = wid / nWM;
    const int row0 = blockIdx.y * 128;
    const int col0 = blockIdx.x * BN;

    // gmem load geometry
    const int arow = tid >> 1;             // 0..127
    const int acol = (tid & 1) * 8;        // 0 or 8
    const int brow = tid >> 4;             // 0..15
    const int bcol = (tid & 15) * BLD;

    float acc[MT][NT][4];
    #pragma unroll
    for (int i = 0; i < MT; i++)
        #pragma unroll
        for (int j = 0; j < NT; j++)
            #pragma unroll
            for (int q = 0; q < 4; q++) acc[i][j][q] = 0.f;

    float apf[8], bpf[BLD];

    auto gload = [&](int k0) {
        const float* Ap = A + (long)(row0 + arow) * lda + k0 + acol;
        *(float4*)(apf)     = *(const float4*)Ap;
        *(float4*)(apf + 4) = *(const float4*)(Ap + 4);
        const float* Bp = Bm + (long)(k0 + brow) * ldb + col0 + bcol;
        *(float4*)(bpf) = *(const float4*)Bp;
        if (BLD == 8) *(float4*)(bpf + 4) = *(const float4*)(Bp + 4);
    };
    auto sstore = [&](int buf) {
        #pragma unroll
        for (int j = 0; j < 8; j++) As[buf][arow][acol + j] = f2tf32(apf[j]);
        #pragma unroll
        for (int j = 0; j < BLD; j++) Bs[buf][brow][bcol + j] = f2tf32(bpf[j]);
    };
    auto compute = [&](int buf) {
        #pragma unroll
        for (int ks = 0; ks < 2; ks++) {
            const int kk = ks * 8;
            uint32_t af[MT][4], bf[NT][2];
            #pragma unroll
            for (int i = 0; i < MT; i++) {
                int r = warp_m * WM + i * 16 + (lane >> 2);
                int c = kk + (lane & 3);
                af[i][0] = As[buf][r][c];
                af[i][1] = As[buf][r + 8][c];
                af[i][2] = As[buf][r][c + 4];
                af[i][3] = As[buf][r + 8][c + 4];
            }
            #pragma unroll
            for (int j = 0; j < NT; j++) {
                int c = warp_n * WN + j * 8 + (lane >> 2);
                bf[j][0] = Bs[buf][kk + (lane & 3)][c];
                bf[j][1] = Bs[buf][kk + 4 + (lane & 3)][c];
            }
            #pragma unroll
            for (int i = 0; i < MT; i++)
                #pragma unroll
                for (int j = 0; j < NT; j++)
                    mma16n8k8(acc[i][j], af[i], bf[j]);
        }
    };

    gload(0);
    sstore(0);
    __syncthreads();

    const int NTL = K / 16;
    for (int kt = 0; kt < NTL; kt++) {
        int buf = kt & 1;
        if (kt + 1 < NTL) gload((kt + 1) * 16);
        compute(buf);
        if (kt + 1 < NTL) sstore(buf ^ 1);
        __syncthreads();
    }

    // epilogue: direct global stores (float2 per fragment half-row)
    #pragma unroll
    for (int i = 0; i < MT; i++) {
        #pragma unroll
        for (int j = 0; j < NT; j++) {
            int r = row0 + warp_m * WM + i * 16 + (lane >> 2);
            int c = col0 + warp_n * WN + j * 8 + 2 * (lane & 3);
            #pragma unroll
            for (int h = 0; h < 2; h++) {
                long rr = r + h * 8;
                float v0 = acc[i][j][2 * h];
                float v1 = acc[i][j][2 * h + 1];
                if (Res) {
                    v0 += Res[rr * (long)ldres + c];
                    v1 += Res[rr * (long)ldres + c + 1];
                }
                if (relu) { v0 = fmaxf(v0, 0.f); v1 = fmaxf(v1, 0.f); }
                *(float2*)&C[rr * (long)ldc + c] = make_float2(v0, v1);
            }
        }
    }
}

// ---------------- positional encoding (fp64 to match numpy) -----------------
__global__ void pe_kernel(float* __restrict__ pe) {
    int idx = blockIdx.x * blockDim.x + threadIdx.x;
    if (idx >= T_ * D_) return;
    int t = idx / D_;
    int d = idx % D_;
    double ang = (double)t * exp(-(2.0 * (double)d / (double)D_) * log(10000.0));
    double v = (d & 1) ? cos(ang) : sin(ang);
    pe[idx] = (float)(v * sqrt((double)D_));
}

__global__ void addpe_kernel(const float* __restrict__ q,
                             const float* __restrict__ pe,
                             float* __restrict__ q1, float* __restrict__ k1) {
    long idx = (long)blockIdx.x * blockDim.x + threadIdx.x;
    long td = idx % ((long)T_ * D_);
    float p = pe[td];
    float a = q[idx] + p;
    q1[idx] = a;
    k1[idx] = a + p;
}

// ---------------- fp32 SIMT GEMM (Q/K proj + scores: precision-critical) ----
constexpr int BM = 128, BNs = 64, BK = 16;

template<bool TB>
__global__ __launch_bounds__(256) void gemm_k(
    const float* __restrict__ A, long sA1, long sA2, int lda,
    const float* __restrict__ Bm, long sB1, long sB2, int ldb,
    float* __restrict__ C, long sC1, long sC2, int ldc,
    int nb2, int K, float alpha)
{
    __shared__ float As[BK][BM + 4];
    __shared__ float Bs[BK][BNs + 4];

    int z  = blockIdx.z;
    int i1 = z / nb2, i2 = z % nb2;
    A  += i1 * sA1 + i2 * sA2;
    Bm += i1 * sB1 + i2 * sB2;
    C  += i1 * sC1 + i2 * sC2;

    int tid = threadIdx.x;
    int tx = tid % 16;
    int ty = tid / 16;
    int row0 = blockIdx.y * BM;
    int col0 = blockIdx.x * BNs;

    float acc[8][4];
    #pragma unroll
    for (int i = 0; i < 8; i++)
        #pragma unroll
        for (int j = 0; j < 4; j++) acc[i][j] = 0.f;

    for (int k0 = 0; k0 < K; k0 += BK) {
        #pragma unroll
        for (int l = 0; l < 8; l++) {
            int idx = tid + l * 256;
            int c = idx % BK;
            int r = idx / BK;
            As[c][r] = A[(long)(row0 + r) * lda + (k0 + c)];
        }
        if (!TB) {
            #pragma unroll
            for (int l = 0; l < 4; l++) {
                int idx = tid + l * 256;
                int n = idx % BNs;
                int c = idx / BNs;
                Bs[c][n] = Bm[(long)(k0 + c) * ldb + (col0 + n)];
            }
        } else {
            #pragma unroll
            for (int l = 0; l < 4; l++) {
                int idx = tid + l * 256;
                int c = idx % BK;
                int n = idx / BK;
                Bs[c][n] = Bm[(long)(col0 + n) * ldb + (k0 + c)];
            }
        }
        __syncthreads();

        #pragma unroll
        for (int kk = 0; kk < BK; kk++) {
            float4 a0 = *(const float4*)&As[kk][ty * 8];
            float4 a1 = *(const float4*)&As[kk][ty * 8 + 4];
            float4 b0 = *(const float4*)&Bs[kk][tx * 4];
            float a[8] = {a0.x, a0.y, a0.z, a0.w, a1.x, a1.y, a1.z, a1.w};
            float b[4] = {b0.x, b0.y, b0.z, b0.w};
            #pragma unroll
            for (int i = 0; i < 8; i++)
                #pragma unroll
                for (int j = 0; j < 4; j++)
                    acc[i][j] = fmaf(a[i], b[j], acc[i][j]);
        }
        __syncthreads();
    }

    #pragma unroll
    for (int i = 0; i < 8; i++) {
        long r = row0 + ty * 8 + i;
        #pragma unroll
        for (int j = 0; j < 4; j++) {
            long c = col0 + tx * 4 + j;
            C[r * (long)ldc + c] = acc[i][j] * alpha;
        }
    }
}

// ---------------- column max over q ------------------------------------------
__global__ __launch_bounds__(256) void colmax_kernel(const float* __restrict__ S,
                                                     float* __restrict__ cmax) {
    int k = blockIdx.x * blockDim.x + threadIdx.x;
    int z = blockIdx.y;
    const float* Sp = S + (long)z * T_ * T_ + k;
    float m = -INFINITY;
    #pragma unroll 4
    for (int q = 0; q < T_; q++) m = fmaxf(m, Sp[(long)q * T_]);
    cmax[(long)z * T_ + k] = m;
}

// ---------------- row softmax of (s - colmax), times qmask -------------------
__global__ __launch_bounds__(256) void softmax_kernel(float* __restrict__ S,
                                                      const float* __restrict__ cmax,
                                                      const int* __restrict__ qmasks) {
    __shared__ float sh[8];
    __shared__ float bc;
    int q = blockIdx.x;
    int z = blockIdx.y;
    int b = z % B_;
    float* row = S + (long)z * T_ * T_ + (long)q * T_;
    const float* cm = cmax + (long)z * T_;
    int tid = threadIdx.x;

    float x0 = row[tid]       - cm[tid];
    float x1 = row[tid + 256] - cm[tid + 256];

    float v = fmaxf(x0, x1);
    #pragma unroll
    for (int o = 16; o; o >>= 1) v = fmaxf(v, __shfl_xor_sync(0xffffffffu, v, o));
    if ((tid & 31) == 0) sh[tid >> 5] = v;
    __syncthreads();
    if (tid == 0) {
        float m = sh[0];
        #pragma unroll
        for (int i = 1; i < 8; i++) m = fmaxf(m, sh[i]);
        bc = m;
    }
    __syncthreads();
    float m = bc;

    float e0 = expf(x0 - m), e1 = expf(x1 - m);
    v = e0 + e1;
    #pragma unroll
    for (int o = 16; o; o >>= 1) v += __shfl_xor_sync(0xffffffffu, v, o);
    __syncthreads();
    if ((tid & 31) == 0) sh[tid >> 5] = v;
    __syncthreads();
    if (tid == 0) {
        float s = 0.f;
        #pragma unroll
        for (int i = 0; i < 8; i++) s += sh[i];
        bc = s;
    }
    __syncthreads();

    float qm  = (q < qmasks[b]) ? 1.f : 0.f;
    float inv = qm / bc;
    row[tid]       = e0 * inv;
    row[tid + 256] = e1 * inv;
}

// ---------------- launch -----------------------------------------------------
extern "C" void kernel_launch(void* const* d_in, const int* in_sizes, int n_in,
                              void* d_out, int out_size) {
    const float* queries = (const float*)d_in[0];
    const int*   qmasks  = (const int*)d_in[2];
    const float* W_Q = (const float*)d_in[4];
    const float* W_K = (const float*)d_in[5];
    const float* W_V = (const float*)d_in[6];
    const float* fw1 = (const float*)d_in[7];
    const float* fw2 = (const float*)d_in[8];
    float* out = (float*)d_out;

    float *pe, *q1, *k1, *Q, *Kp, *V, *S, *cmax, *R, *hidden;
    cudaGetSymbolAddress((void**)&pe, g_pe);
    cudaGetSymbolAddress((void**)&q1, g_q1);
    cudaGetSymbolAddress((void**)&k1, g_k1);
    cudaGetSymbolAddress((void**)&Q,  g_Q);
    cudaGetSymbolAddress((void**)&Kp, g_K);
    cudaGetSymbolAddress((void**)&V,  g_V);
    cudaGetSymbolAddress((void**)&S,  g_S);
    cudaGetSymbolAddress((void**)&cmax, g_cmax);
    cudaGetSymbolAddress((void**)&R,  g_R);
    cudaGetSymbolAddress((void**)&hidden, g_hidden);

    const long TD = (long)T_ * D_;
    const long TT = (long)T_ * T_;

    // 1) posenc
    pe_kernel<<<(T_ * D_ + 255) / 256, 256>>>(pe);
    addpe_kernel<<<(B_ * T_ * D_) / 256, 256>>>(queries, pe, q1, k1);

    // 2) Q/K projections (fp32 SIMT: precision-critical)
    {
        dim3 g(D_ / BNs, (B_ * T_) / BM, 1);
        gemm_k<false><<<g, 256>>>(q1, 0, 0, D_, W_Q, 0, 0, D_, Q, 0, 0, D_, 1, D_, 1.f);
        gemm_k<false><<<g, 256>>>(k1, 0, 0, D_, W_K, 0, 0, D_, Kp, 0, 0, D_, 1, D_, 1.f);
    }

    // 3) V projection on tensor cores (tf32): V = Kp @ W_V (bug kept)
    {
        dim3 g(D_ / 128, (B_ * T_) / 128, 1);
        mma_gemm<128><<<g, 256>>>(Kp, 0, 0, D_, W_V, 0, 0, D_,
                                  V, 0, 0, D_, nullptr, 0, 0, 0, 1, D_, 0);
    }

    // 4) scores (fp32 SIMT: precision-critical near-argmax softmax)
    {
        dim3 g(T_ / BNs, T_ / BM, HB_);
        gemm_k<true><<<g, 256>>>(Q,  DH_, TD, D_,
                                 Kp, DH_, TD, D_,
                                 S,  (long)B_ * TT, TT, T_,
                                 B_, DH_, 0.125f);
    }

    // 5) colmax + softmax
    colmax_kernel<<<dim3(T_ / 256, HB_), 256>>>(S, cmax);
    softmax_kernel<<<dim3(T_, HB_), 256>>>(S, cmax, qmasks);

    // 6) AV (tf32 tensor): R = attn @ Vh + q1; B = V in natural [t][d] layout
    {
        dim3 g(1, T_ / 128, HB_);
        mma_gemm<64><<<g, 256>>>(S, (long)B_ * TT, TT, T_,
                                 V, DH_, TD, D_,
                                 R, DH_, TD, D_,
                                 q1, DH_, TD, D_,
                                 B_, T_, 0);
    }

    // 7) FFN1 (tf32 tensor): hidden = relu(R @ fw1)
    {
        dim3 g(FF_ / 128, (B_ * T_) / 128, 1);
        mma_gemm<128><<<g, 256>>>(R, 0, 0, D_, fw1, 0, 0, FF_,
                                  hidden, 0, 0, FF_, nullptr, 0, 0, 0, 1, D_, 1);
    }

    // 8) FFN2 (tf32 tensor): out = R + hidden @ fw2
    {
        dim3 g(D_ / 128, (B_ * T_) / 128, 1);
        mma_gemm<128><<<g, 256>>>(hidden, 0, 0, FF_, fw2, 0, 0, D_,
                                  out, 0, 0, D_, R, 0, 0, D_, 1, FF_, 0);
    }
}

// round 4
// speedup vs baseline: 1.8552x; 1.0993x over previous
#include <cuda_runtime.h>
#include <math.h>
#include <stdint.h>

// Problem constants
constexpr int B_  = 32;
constexpr int T_  = 512;
constexpr int D_  = 512;
constexpr int H_  = 8;
constexpr int DH_ = 64;
constexpr int HB_ = H_ * B_;        // 256
constexpr int FF_ = 4 * D_;         // 2048

// ---------------- scratch (static device globals; allocation-free) ----------
__device__ float g_pe[T_ * D_];
__device__ float g_q1[B_ * T_ * D_];
__device__ float g_k1[B_ * T_ * D_];
__device__ float g_Q [B_ * T_ * D_];
__device__ float g_K [B_ * T_ * D_];
__device__ float g_V [B_ * T_ * D_];
__device__ float g_S [(long)HB_ * T_ * T_];        // 256MB
__device__ float g_cmax[HB_ * T_];
__device__ float g_R [B_ * T_ * D_];
__device__ float g_hidden[(long)B_ * T_ * FF_];    // 128MB

// ---------------- helpers ---------------------------------------------------
__device__ __forceinline__ uint32_t f2tf32(float f) {
    uint32_t u;
    asm("cvt.rna.tf32.f32 %0, %1;" : "=r"(u) : "f"(f));
    return u;
}
__device__ __forceinline__ void mma16n8k8(float* c, const uint32_t* a, const uint32_t* b) {
    asm volatile(
        "mma.sync.aligned.m16n8k8.row.col.f32.tf32.tf32.f32 "
        "{%0,%1,%2,%3}, {%4,%5,%6,%7}, {%8,%9}, {%0,%1,%2,%3};"
        : "+f"(c[0]), "+f"(c[1]), "+f"(c[2]), "+f"(c[3])
        : "r"(a[0]), "r"(a[1]), "r"(a[2]), "r"(a[3]), "r"(b[0]), "r"(b[1]));
}

// ============ tf32 mma.sync GEMM engine v2 ==================================
// C[128 x BN tile] = alpha * A[M,K] @ B + (Res) (relu)
// A row-major (lda). B: TBB=0 -> [K][N] (N contig); TBB=1 -> [N][K] (K contig).
// SPLIT=1: 3xTF32 error-compensated (hi/lo planes, BK=16). SPLIT=0: BK=32.
template<int BN, bool TBB, bool SPLIT>
__global__ void __launch_bounds__(256, SPLIT ? 1 : 2) mma2(
    const float* __restrict__ A, long sA1, long sA2, int lda,
    const float* __restrict__ Bm, long sB1, long sB2, int ldb,
    float* __restrict__ C, long sC1, long sC2, int ldc,
    const float* __restrict__ Res, long sR1, long sR2, int ldres,
    int nb2, int K, float alpha, int relu)
{
    constexpr int BK  = SPLIT ? 16 : 32;
    constexpr int AP  = BK + 4;            // A smem pitch (frag loads conflict-free)
    constexpr int BP  = BN + 8;            // B smem pitch
    constexpr int NSP = SPLIT ? 2 : 1;     // planes (hi, lo)
    constexpr int nWN = (BN == 128) ? 4 : 2;
    constexpr int nWM = 8 / nWN;
    constexpr int WM  = 128 / nWM;
    constexpr int WN  = BN / nWN;
    constexpr int MT  = WM / 16;
    constexpr int NT  = WN / 8;
    constexpr int FA  = BK / 2;                       // A floats / thread / tile
    constexpr int FB  = TBB ? 8 : (BK * BN / 256);    // B floats / thread / tile

    extern __shared__ uint32_t sm[];
    uint32_t* Asm = sm;                               // [2][NSP][128*AP]
    uint32_t* Bsm = sm + 2 * NSP * 128 * AP;          // [2][NSP][BK*BP]

    int z  = blockIdx.z;
    int i1 = z / nb2, i2 = z % nb2;
    A  += i1 * sA1 + i2 * sA2;
    Bm += i1 * sB1 + i2 * sB2;
    C  += i1 * sC1 + i2 * sC2;
    if (Res) Res += i1 * sR1 + i2 * sR2;

    const int tid  = threadIdx.x;
    const int lane = tid & 31;
    const int wid  = tid >> 5;
    const int warp_m = wid % nWM;
    const int warp_n = wid / nWM;
    const int row0 = blockIdx.y * 128;
    const int col0 = blockIdx.x * BN;

    // gmem geometry
    const int arow = tid >> 1;
    const int acol = (tid & 1) * FA;
    constexpr int TPR = TBB ? 0 : (BN / FB);
    const int brow = TBB ? (tid >> 1) : (tid / (TPR ? TPR : 1));   // TBB: n-row
    const int bcol = TBB ? ((tid & 1) * 8) : ((tid % (TPR ? TPR : 1)) * FB);

    float acc[MT][NT][4];
    #pragma unroll
    for (int i = 0; i < MT; i++)
        #pragma unroll
        for (int j = 0; j < NT; j++)
            #pragma unroll
            for (int q = 0; q < 4; q++) acc[i][j][q] = 0.f;

    float apf[FA], bpf[FB];

    auto gload = [&](int k0) {
        const float* Ap = A + (long)(row0 + arow) * lda + k0 + acol;
        #pragma unroll
        for (int j = 0; j < FA / 4; j++)
            *(float4*)(apf + 4 * j) = *(const float4*)(Ap + 4 * j);
        if (TBB) {
            const float* Bp = Bm + (long)(col0 + brow) * ldb + k0 + bcol;
            #pragma unroll
            for (int j = 0; j < FB / 4; j++)
                *(float4*)(bpf + 4 * j) = *(const float4*)(Bp + 4 * j);
        } else {
            const float* Bp = Bm + (long)(k0 + brow) * ldb + col0 + bcol;
            #pragma unroll
            for (int j = 0; j < FB / 4; j++)
                *(float4*)(bpf + 4 * j) = *(const float4*)(Bp + 4 * j);
        }
    };
    auto sstore = [&](int buf) {
        uint32_t* Ah = Asm + (buf * NSP) * 128 * AP;
        #pragma unroll
        for (int j = 0; j < FA; j++) {
            uint32_t u = f2tf32(apf[j]);
            Ah[arow * AP + acol + j] = u;
            if (SPLIT) {
                uint32_t l = f2tf32(apf[j] - __uint_as_float(u));
                Ah[128 * AP + arow * AP + acol + j] = l;
            }
        }
        uint32_t* Bh = Bsm + (buf * NSP) * BK * BP;
        #pragma unroll
        for (int j = 0; j < FB; j++) {
            uint32_t u = f2tf32(bpf[j]);
            uint32_t l = 0;
            if (SPLIT) l = f2tf32(bpf[j] - __uint_as_float(u));
            if (TBB) {
                Bh[(bcol + j) * BP + brow] = u;
                if (SPLIT) Bh[BK * BP + (bcol + j) * BP + brow] = l;
            } else {
                Bh[brow * BP + bcol + j] = u;
                if (SPLIT) Bh[BK * BP + brow * BP + bcol + j] = l;
            }
        }
    };
    auto compute = [&](int buf) {
        const uint32_t* Ah = Asm + (buf * NSP) * 128 * AP;
        const uint32_t* Al = Ah + 128 * AP;
        const uint32_t* Bh = Bsm + (buf * NSP) * BK * BP;
        const uint32_t* Bl = Bh + BK * BP;
        const int frow = lane >> 2, fcol = lane & 3;
        #pragma unroll
        for (int ks = 0; ks < BK / 8; ks++) {
            const int kk = ks * 8;
            uint32_t ah[MT][4], bh[NT][2];
            uint32_t al[MT][4], bl[NT][2];
            #pragma unroll
            for (int i = 0; i < MT; i++) {
                int r = warp_m * WM + i * 16 + frow;
                int c = kk + fcol;
                ah[i][0] = Ah[r * AP + c];
                ah[i][1] = Ah[(r + 8) * AP + c];
                ah[i][2] = Ah[r * AP + c + 4];
                ah[i][3] = Ah[(r + 8) * AP + c + 4];
                if (SPLIT) {
                    al[i][0] = Al[r * AP + c];
                    al[i][1] = Al[(r + 8) * AP + c];
                    al[i][2] = Al[r * AP + c + 4];
                    al[i][3] = Al[(r + 8) * AP + c + 4];
                }
            }
            #pragma unroll
            for (int j = 0; j < NT; j++) {
                int c = warp_n * WN + j * 8 + frow;
                bh[j][0] = Bh[(kk + fcol) * BP + c];
                bh[j][1] = Bh[(kk + 4 + fcol) * BP + c];
                if (SPLIT) {
                    bl[j][0] = Bl[(kk + fcol) * BP + c];
                    bl[j][1] = Bl[(kk + 4 + fcol) * BP + c];
                }
            }
            #pragma unroll
            for (int i = 0; i < MT; i++)
                #pragma unroll
                for (int j = 0; j < NT; j++) {
                    mma16n8k8(acc[i][j], ah[i], bh[j]);
                    if (SPLIT) {
                        mma16n8k8(acc[i][j], ah[i], bl[j]);
                        mma16n8k8(acc[i][j], al[i], bh[j]);
                    }
                }
        }
    };

    gload(0);
    sstore(0);
    __syncthreads();

    const int NTL = K / BK;
    for (int kt = 0; kt < NTL; kt++) {
        int buf = kt & 1;
        if (kt + 1 < NTL) gload((kt + 1) * BK);
        compute(buf);
        if (kt + 1 < NTL) sstore(buf ^ 1);
        __syncthreads();
    }

    // epilogue: alpha, residual, relu, direct float2 stores
    #pragma unroll
    for (int i = 0; i < MT; i++) {
        #pragma unroll
        for (int j = 0; j < NT; j++) {
            int r = row0 + warp_m * WM + i * 16 + (lane >> 2);
            int c = col0 + warp_n * WN + j * 8 + 2 * (lane & 3);
            #pragma unroll
            for (int h = 0; h < 2; h++) {
                long rr = r + h * 8;
                float v0 = acc[i][j][2 * h] * alpha;
                float v1 = acc[i][j][2 * h + 1] * alpha;
                if (Res) {
                    v0 += Res[rr * (long)ldres + c];
                    v1 += Res[rr * (long)ldres + c + 1];
                }
                if (relu) { v0 = fmaxf(v0, 0.f); v1 = fmaxf(v1, 0.f); }
                *(float2*)&C[rr * (long)ldc + c] = make_float2(v0, v1);
            }
        }
    }
}

// smem bytes per instantiation
constexpr int smem_bytes(int BN, bool SPLIT) {
    int BK = SPLIT ? 16 : 32, AP = BK + 4, BP = BN + 8, NSP = SPLIT ? 2 : 1;
    return 4 * (2 * NSP * 128 * AP + 2 * NSP * BK * BP);
}

// ---------------- positional encoding (fp64 to match numpy) -----------------
__global__ void pe_kernel(float* __restrict__ pe) {
    int idx = blockIdx.x * blockDim.x + threadIdx.x;
    if (idx >= T_ * D_) return;
    int t = idx / D_;
    int d = idx % D_;
    double ang = (double)t * exp(-(2.0 * (double)d / (double)D_) * log(10000.0));
    double v = (d & 1) ? cos(ang) : sin(ang);
    pe[idx] = (float)(v * sqrt((double)D_));
}

__global__ void addpe_kernel(const float* __restrict__ q,
                             const float* __restrict__ pe,
                             float* __restrict__ q1, float* __restrict__ k1) {
    long idx = (long)blockIdx.x * blockDim.x + threadIdx.x;
    long td = idx % ((long)T_ * D_);
    float p = pe[td];
    float a = q[idx] + p;
    q1[idx] = a;
    k1[idx] = a + p;
}

// ---------------- column max over q ------------------------------------------
__global__ __launch_bounds__(256) void colmax_kernel(const float* __restrict__ S,
                                                     float* __restrict__ cmax) {
    int k = blockIdx.x * blockDim.x + threadIdx.x;
    int z = blockIdx.y;
    const float* Sp = S + (long)z * T_ * T_ + k;
    float m = -INFINITY;
    #pragma unroll 4
    for (int q = 0; q < T_; q++) m = fmaxf(m, Sp[(long)q * T_]);
    cmax[(long)z * T_ + k] = m;
}

// ---------------- row softmax of (s - colmax), times qmask -------------------
__global__ __launch_bounds__(256) void softmax_kernel(float* __restrict__ S,
                                                      const float* __restrict__ cmax,
                                                      const int* __restrict__ qmasks) {
    __shared__ float sh[8];
    __shared__ float bc;
    int q = blockIdx.x;
    int z = blockIdx.y;
    int b = z % B_;
    float* row = S + (long)z * T_ * T_ + (long)q * T_;
    const float* cm = cmax + (long)z * T_;
    int tid = threadIdx.x;

    float x0 = row[tid]       - cm[tid];
    float x1 = row[tid + 256] - cm[tid + 256];

    float v = fmaxf(x0, x1);
    #pragma unroll
    for (int o = 16; o; o >>= 1) v = fmaxf(v, __shfl_xor_sync(0xffffffffu, v, o));
    if ((tid & 31) == 0) sh[tid >> 5] = v;
    __syncthreads();
    if (tid == 0) {
        float m = sh[0];
        #pragma unroll
        for (int i = 1; i < 8; i++) m = fmaxf(m, sh[i]);
        bc = m;
    }
    __syncthreads();
    float m = bc;

    float e0 = expf(x0 - m), e1 = expf(x1 - m);
    v = e0 + e1;
    #pragma unroll
    for (int o = 16; o; o >>= 1) v += __shfl_xor_sync(0xffffffffu, v, o);
    __syncthreads();
    if ((tid & 31) == 0) sh[tid >> 5] = v;
    __syncthreads();
    if (tid == 0) {
        float s = 0.f;
        #pragma unroll
        for (int i = 0; i < 8; i++) s += sh[i];
        bc = s;
    }
    __syncthreads();

    float qm  = (q < qmasks[b]) ? 1.f : 0.f;
    float inv = qm / bc;
    row[tid]       = e0 * inv;
    row[tid + 256] = e1 * inv;
}

// ---------------- launch -----------------------------------------------------
extern "C" void kernel_launch(void* const* d_in, const int* in_sizes, int n_in,
                              void* d_out, int out_size) {
    const float* queries = (const float*)d_in[0];
    const int*   qmasks  = (const int*)d_in[2];
    const float* W_Q = (const float*)d_in[4];
    const float* W_K = (const float*)d_in[5];
    const float* W_V = (const float*)d_in[6];
    const float* fw1 = (const float*)d_in[7];
    const float* fw2 = (const float*)d_in[8];
    float* out = (float*)d_out;

    float *pe, *q1, *k1, *Q, *Kp, *V, *S, *cmax, *R, *hidden;
    cudaGetSymbolAddress((void**)&pe, g_pe);
    cudaGetSymbolAddress((void**)&q1, g_q1);
    cudaGetSymbolAddress((void**)&k1, g_k1);
    cudaGetSymbolAddress((void**)&Q,  g_Q);
    cudaGetSymbolAddress((void**)&Kp, g_K);
    cudaGetSymbolAddress((void**)&V,  g_V);
    cudaGetSymbolAddress((void**)&S,  g_S);
    cudaGetSymbolAddress((void**)&cmax, g_cmax);
    cudaGetSymbolAddress((void**)&R,  g_R);
    cudaGetSymbolAddress((void**)&hidden, g_hidden);

    const long TD = (long)T_ * D_;
    const long TT = (long)T_ * T_;

    constexpr int SM_P128 = smem_bytes(128, false);  // 71680
    constexpr int SM_P64  = smem_bytes(64,  false);  // 55296
    constexpr int SM_S128 = smem_bytes(128, true);   // 75776

    cudaFuncSetAttribute(mma2<128, false, false>, cudaFuncAttributeMaxDynamicSharedMemorySize, SM_P128);
    cudaFuncSetAttribute(mma2<64,  false, false>, cudaFuncAttributeMaxDynamicSharedMemorySize, SM_P64);
    cudaFuncSetAttribute(mma2<128, false, true>,  cudaFuncAttributeMaxDynamicSharedMemorySize, SM_S128);
    cudaFuncSetAttribute(mma2<128, true,  true>,  cudaFuncAttributeMaxDynamicSharedMemorySize, SM_S128);

    // 1) posenc
    pe_kernel<<<(T_ * D_ + 255) / 256, 256>>>(pe);
    addpe_kernel<<<(B_ * T_ * D_) / 256, 256>>>(queries, pe, q1, k1);

    // 2) Q/K projections (3xTF32 split: precision-critical)
    {
        dim3 g(D_ / 128, (B_ * T_) / 128, 1);
        mma2<128, false, true><<<g, 256, SM_S128>>>(
            q1, 0, 0, D_, W_Q, 0, 0, D_, Q, 0, 0, D_,
            nullptr, 0, 0, 0, 1, D_, 1.f, 0);
        mma2<128, false, true><<<g, 256, SM_S128>>>(
            k1, 0, 0, D_, W_K, 0, 0, D_, Kp, 0, 0, D_,
            nullptr, 0, 0, 0, 1, D_, 1.f, 0);
    }

    // 3) V projection (single tf32): V = Kp @ W_V (bug kept)
    {
        dim3 g(D_ / 128, (B_ * T_) / 128, 1);
        mma2<128, false, false><<<g, 256, SM_P128>>>(
            Kp, 0, 0, D_, W_V, 0, 0, D_, V, 0, 0, D_,
            nullptr, 0, 0, 0, 1, D_, 1.f, 0);
    }

    // 4) scores (3xTF32 split): S[z] = Qh @ Kh^T / 8 ; B operand is [N][K]
    {
        dim3 g(T_ / 128, T_ / 128, HB_);
        mma2<128, true, true><<<g, 256, SM_S128>>>(
            Q,  DH_, TD, D_,
            Kp, DH_, TD, D_,
            S,  (long)B_ * TT, TT, T_,
            nullptr, 0, 0, 0,
            B_, DH_, 0.125f, 0);
    }

    // 5) colmax + softmax
    colmax_kernel<<<dim3(T_ / 256, HB_), 256>>>(S, cmax);
    softmax_kernel<<<dim3(T_, HB_), 256>>>(S, cmax, qmasks);

    // 6) AV (single tf32): R = attn @ Vh + q1 residual
    {
        dim3 g(1, T_ / 128, HB_);
        mma2<64, false, false><<<g, 256, SM_P64>>>(
            S, (long)B_ * TT, TT, T_,
            V, DH_, TD, D_,
            R, DH_, TD, D_,
            q1, DH_, TD, D_,
            B_, T_, 1.f, 0);
    }

    // 7) FFN1 (single tf32): hidden = relu(R @ fw1)
    {
        dim3 g(FF_ / 128, (B_ * T_) / 128, 1);
        mma2<128, false, false><<<g, 256, SM_P128>>>(
            R, 0, 0, D_, fw1, 0, 0, FF_, hidden, 0, 0, FF_,
            nullptr, 0, 0, 0, 1, D_, 1.f, 1);
    }

    // 8) FFN2 (single tf32): out = R + hidden @ fw2
    {
        dim3 g(D_ / 128, (B_ * T_) / 128, 1);
        mma2<128, false, false><<<g, 256, SM_P128>>>(
            hidden, 0, 0, FF_, fw2, 0, 0, D_, out, 0, 0, D_,
            R, 0, 0, D_, 1, FF_, 1.f, 0);
    }
}

// round 5
// speedup vs baseline: 2.1831x; 1.1768x over previous
#include <cuda_runtime.h>
#include <math.h>
#include <stdint.h>

// Problem constants
constexpr int B_  = 32;
constexpr int T_  = 512;
constexpr int D_  = 512;
constexpr int H_  = 8;
constexpr int DH_ = 64;
constexpr int HB_ = H_ * B_;        // 256
constexpr int FF_ = 4 * D_;         // 2048

// ---------------- scratch (static device globals; allocation-free) ----------
__device__ float    g_pe [T_ * D_];
__device__ float    g_q1 [B_ * T_ * D_];            // fp32 residual
__device__ uint32_t g_q1h[B_ * T_ * D_];
__device__ uint32_t g_q1l[B_ * T_ * D_];
__device__ uint32_t g_k1h[B_ * T_ * D_];
__device__ uint32_t g_k1l[B_ * T_ * D_];
__device__ uint32_t g_Qh [B_ * T_ * D_];
__device__ uint32_t g_Ql [B_ * T_ * D_];
__device__ uint32_t g_Kh [B_ * T_ * D_];
__device__ uint32_t g_Kl [B_ * T_ * D_];
__device__ uint32_t g_Vh [B_ * T_ * D_];
__device__ float    g_S  [(long)HB_ * T_ * T_];     // 256MB (fp32, then tf32 bits)
__device__ float    g_cmax[HB_ * T_];
__device__ float    g_R  [B_ * T_ * D_];            // fp32 residual
__device__ uint32_t g_Rh [B_ * T_ * D_];
__device__ uint32_t g_H  [(long)B_ * T_ * FF_];     // hidden, tf32 bits, 128MB
// converted weights
__device__ uint32_t g_wqh[D_ * D_], g_wql[D_ * D_];
__device__ uint32_t g_wkh[D_ * D_], g_wkl[D_ * D_];
__device__ uint32_t g_wvh[D_ * D_];
__device__ uint32_t g_f1h[D_ * FF_];
__device__ uint32_t g_f2h[FF_ * D_];

// ---------------- helpers ---------------------------------------------------
__device__ __forceinline__ uint32_t f2tf32(float f) {
    uint32_t u;
    asm("cvt.rna.tf32.f32 %0, %1;" : "=r"(u) : "f"(f));
    return u;
}
__device__ __forceinline__ void mma16n8k8(float* c, const uint32_t* a, const uint32_t* b) {
    asm volatile(
        "mma.sync.aligned.m16n8k8.row.col.f32.tf32.tf32.f32 "
        "{%0,%1,%2,%3}, {%4,%5,%6,%7}, {%8,%9}, {%0,%1,%2,%3};"
        : "+f"(c[0]), "+f"(c[1]), "+f"(c[2]), "+f"(c[3])
        : "r"(a[0]), "r"(a[1]), "r"(a[2]), "r"(a[3]), "r"(b[0]), "r"(b[1]));
}
__device__ __forceinline__ uint32_t smem_u32(const void* p) {
    uint32_t a;
    asm("{ .reg .u64 t; cvta.to.shared.u64 t, %1; cvt.u32.u64 %0, t; }"
        : "=r"(a) : "l"(p));
    return a;
}
__device__ __forceinline__ void cpa16(uint32_t saddr, const void* g) {
    asm volatile("cp.async.ca.shared.global [%0], [%1], 16;"
                 :: "r"(saddr), "l"(g) : "memory");
}
#define CPA_COMMIT() asm volatile("cp.async.commit_group;" ::: "memory")
#define CPA_WAIT1()  asm volatile("cp.async.wait_group 1;" ::: "memory")

// ============ tf32 mma.sync GEMM engine v3 (cp.async, preconverted) =========
// All operands are tf32 bit-images in gmem. A row-major (lda).
// B: TBB=0 -> [K][N]; TBB=1 -> [N][K]. SPLIT=1: 3xTF32 with hi/lo planes.
// OUT: 0 = fp32; 1 = tf32 hi; 2 = tf32 hi+lo; 3 = fp32 + tf32 hi.
template<int BN, bool TBB, bool SPLIT, int OUT>
__global__ void __launch_bounds__(256, SPLIT ? 1 : 2) mma3(
    const uint32_t* __restrict__ Ah_g, const uint32_t* __restrict__ Al_g,
    long sA1, long sA2, int lda,
    const uint32_t* __restrict__ Bh_g, const uint32_t* __restrict__ Bl_g,
    long sB1, long sB2, int ldb,
    float* Cf, uint32_t* Chi, uint32_t* Clo, long sC1, long sC2, int ldc,
    const float* __restrict__ Res, long sR1, long sR2, int ldres,
    int nb2, int K, float alpha, int relu)
{
    constexpr int BK   = SPLIT ? 16 : 32;
    constexpr int S    = 3;
    constexpr int AP   = BK + 4;               // A (and TBB-B) smem pitch
    constexpr int APL  = 128 * AP;             // per-plane A size (u32)
    constexpr int ASZ  = (SPLIT ? 2 : 1) * APL;
    constexpr int BPKN = BN + 8;               // [K][N] B pitch
    constexpr int BPL  = TBB ? APL : BK * BPKN;
    constexpr int BSZ  = (SPLIT ? 2 : 1) * BPL;
    constexpr int ACH  = (128 * (BK / 4) * (SPLIT ? 2 : 1)) / 256;
    constexpr int BCH  = TBB ? ACH : ((BK * (BN / 4) * (SPLIT ? 2 : 1)) / 256);
    constexpr int nWN  = (BN == 128) ? 4 : 2;
    constexpr int nWM  = 8 / nWN;
    constexpr int WM   = 128 / nWM;
    constexpr int WN   = BN / nWN;
    constexpr int MT   = WM / 16;
    constexpr int NT   = WN / 8;

    extern __shared__ uint32_t sm[];
    const uint32_t sbase = smem_u32(sm);

    int z  = blockIdx.z;
    int i1 = z / nb2, i2 = z % nb2;
    Ah_g += i1 * sA1 + i2 * sA2;
    if (SPLIT) Al_g += i1 * sA1 + i2 * sA2;
    Bh_g += i1 * sB1 + i2 * sB2;
    if (SPLIT) Bl_g += i1 * sB1 + i2 * sB2;
    if (OUT == 0 || OUT == 3) Cf  += i1 * sC1 + i2 * sC2;
    if (OUT >= 1)             Chi += i1 * sC1 + i2 * sC2;
    if (OUT == 2)             Clo += i1 * sC1 + i2 * sC2;
    if (Res) Res += i1 * sR1 + i2 * sR2;

    const int tid  = threadIdx.x;
    const int lane = tid & 31;
    const int wid  = tid >> 5;
    const int warp_m = wid % nWM;
    const int warp_n = wid / nWM;
    const int row0 = blockIdx.y * 128;
    const int col0 = blockIdx.x * BN;
    const int frow = lane >> 2, fcol = lane & 3;

    float acc[MT][NT][4];
    #pragma unroll
    for (int i = 0; i < MT; i++)
        #pragma unroll
        for (int j = 0; j < NT; j++)
            #pragma unroll
            for (int q = 0; q < 4; q++) acc[i][j][q] = 0.f;

    auto load_stage = [&](int st, int k0) {
        uint32_t sA = sbase + (uint32_t)(st * ASZ) * 4;
        #pragma unroll
        for (int i = 0; i < ACH; i++) {
            int idx = i * 256 + tid;
            int plane = SPLIT ? (idx >= 128 * (BK / 4) ? 1 : 0) : 0;
            int rem = idx - plane * 128 * (BK / 4);
            int row = rem / (BK / 4), c = rem % (BK / 4);
            const uint32_t* g = (plane ? Al_g : Ah_g)
                              + (long)(row0 + row) * lda + k0 + c * 4;
            cpa16(sA + (uint32_t)(plane * APL + row * AP + c * 4) * 4, g);
        }
        uint32_t sB = sbase + (uint32_t)(S * ASZ + st * BSZ) * 4;
        if (TBB) {
            #pragma unroll
            for (int i = 0; i < BCH; i++) {
                int idx = i * 256 + tid;
                int plane = SPLIT ? (idx >= 128 * (BK / 4) ? 1 : 0) : 0;
                int rem = idx - plane * 128 * (BK / 4);
                int row = rem / (BK / 4), c = rem % (BK / 4);
                const uint32_t* g = (plane ? Bl_g : Bh_g)
                                  + (long)(col0 + row) * ldb + k0 + c * 4;
                cpa16(sB + (uint32_t)(plane * BPL + row * AP + c * 4) * 4, g);
            }
        } else {
            #pragma unroll
            for (int i = 0; i < BCH; i++) {
                int idx = i * 256 + tid;
                int plane = SPLIT ? (idx >= BK * (BN / 4) ? 1 : 0) : 0;
                int rem = idx - plane * BK * (BN / 4);
                int row = rem / (BN / 4), c = rem % (BN / 4);
                const uint32_t* g = (plane ? Bl_g : Bh_g)
                                  + (long)(k0 + row) * ldb + col0 + c * 4;
                cpa16(sB + (uint32_t)(plane * BPL + row * BPKN + c * 4) * 4, g);
            }
        }
    };

    auto compute = [&](int st) {
        const uint32_t* As_h = sm + st * ASZ;
        const uint32_t* As_l = As_h + APL;
        const uint32_t* Bs_h = sm + S * ASZ + st * BSZ;
        const uint32_t* Bs_l = Bs_h + BPL;
        #pragma unroll
        for (int ks = 0; ks < BK / 8; ks++) {
            const int kk = ks * 8;
            uint32_t ah[MT][4], bh[NT][2];
            uint32_t al[MT][4], bl[NT][2];
            #pragma unroll
            for (int i = 0; i < MT; i++) {
                int r = warp_m * WM + i * 16 + frow;
                int c = kk + fcol;
                ah[i][0] = As_h[r * AP + c];
                ah[i][1] = As_h[(r + 8) * AP + c];
                ah[i][2] = As_h[r * AP + c + 4];
                ah[i][3] = As_h[(r + 8) * AP + c + 4];
                if (SPLIT) {
                    al[i][0] = As_l[r * AP + c];
                    al[i][1] = As_l[(r + 8) * AP + c];
                    al[i][2] = As_l[r * AP + c + 4];
                    al[i][3] = As_l[(r + 8) * AP + c + 4];
                }
            }
            #pragma unroll
            for (int j = 0; j < NT; j++) {
                int n = warp_n * WN + j * 8 + frow;
                if (TBB) {
                    bh[j][0] = Bs_h[n * AP + kk + fcol];
                    bh[j][1] = Bs_h[n * AP + kk + 4 + fcol];
                    if (SPLIT) {
                        bl[j][0] = Bs_l[n * AP + kk + fcol];
                        bl[j][1] = Bs_l[n * AP + kk + 4 + fcol];
                    }
                } else {
                    bh[j][0] = Bs_h[(kk + fcol) * BPKN + n];
                    bh[j][1] = Bs_h[(kk + 4 + fcol) * BPKN + n];
                    if (SPLIT) {
                        bl[j][0] = Bs_l[(kk + fcol) * BPKN + n];
                        bl[j][1] = Bs_l[(kk + 4 + fcol) * BPKN + n];
                    }
                }
            }
            #pragma unroll
            for (int i = 0; i < MT; i++)
                #pragma unroll
                for (int j = 0; j < NT; j++) {
                    mma16n8k8(acc[i][j], ah[i], bh[j]);
                    if (SPLIT) {
                        mma16n8k8(acc[i][j], ah[i], bl[j]);
                        mma16n8k8(acc[i][j], al[i], bh[j]);
                    }
                }
        }
    };

    const int NTL = K / BK;
    load_stage(0, 0);       CPA_COMMIT();
    load_stage(1, BK);      CPA_COMMIT();

    for (int kt = 0; kt < NTL; kt++) {
        CPA_WAIT1();
        __syncthreads();
        if (kt + 2 < NTL) load_stage((kt + 2) % S, (kt + 2) * BK);
        CPA_COMMIT();
        compute(kt % S);
    }

    // epilogue
    #pragma unroll
    for (int i = 0; i < MT; i++) {
        #pragma unroll
        for (int j = 0; j < NT; j++) {
            int r = row0 + warp_m * WM + i * 16 + frow;
            int c = col0 + warp_n * WN + j * 8 + 2 * fcol;
            #pragma unroll
            for (int h = 0; h < 2; h++) {
                long rr = r + h * 8;
                float v0 = acc[i][j][2 * h] * alpha;
                float v1 = acc[i][j][2 * h + 1] * alpha;
                if (Res) {
                    v0 += Res[rr * (long)ldres + c];
                    v1 += Res[rr * (long)ldres + c + 1];
                }
                if (relu) { v0 = fmaxf(v0, 0.f); v1 = fmaxf(v1, 0.f); }
                if (OUT == 0 || OUT == 3)
                    *(float2*)&Cf[rr * (long)ldc + c] = make_float2(v0, v1);
                if (OUT >= 1) {
                    uint32_t h0 = f2tf32(v0), h1 = f2tf32(v1);
                    uint2 hv; hv.x = h0; hv.y = h1;
                    *(uint2*)&Chi[rr * (long)ldc + c] = hv;
                    if (OUT == 2) {
                        uint2 lv;
                        lv.x = f2tf32(v0 - __uint_as_float(h0));
                        lv.y = f2tf32(v1 - __uint_as_float(h1));
                        *(uint2*)&Clo[rr * (long)ldc + c] = lv;
                    }
                }
            }
        }
    }
}

constexpr int smem3(int BN, bool TBB, bool SPLIT) {
    int BK = SPLIT ? 16 : 32, AP = BK + 4;
    int APL = 128 * AP, ASZ = (SPLIT ? 2 : 1) * APL;
    int BPL = TBB ? APL : BK * (BN + 8);
    int BSZ = (SPLIT ? 2 : 1) * BPL;
    return 4 * 3 * (ASZ + BSZ);
}

// ---------------- positional encoding (fp64 to match numpy) -----------------
__global__ void pe_kernel(float* __restrict__ pe) {
    int idx = blockIdx.x * blockDim.x + threadIdx.x;
    if (idx >= T_ * D_) return;
    int t = idx / D_;
    int d = idx % D_;
    double ang = (double)t * exp(-(2.0 * (double)d / (double)D_) * log(10000.0));
    double v = (d & 1) ? cos(ang) : sin(ang);
    pe[idx] = (float)(v * sqrt((double)D_));
}

// addpe + hi/lo split of q1 and k1
__global__ void addpe2_kernel(const float* __restrict__ q, const float* __restrict__ pe,
                              float* __restrict__ q1f,
                              uint32_t* __restrict__ q1h, uint32_t* __restrict__ q1l,
                              uint32_t* __restrict__ k1h, uint32_t* __restrict__ k1l) {
    long idx = (long)blockIdx.x * blockDim.x + threadIdx.x;
    long td = idx % ((long)T_ * D_);
    float p = pe[td];
    float a = q[idx] + p;
    q1f[idx] = a;
    uint32_t ah = f2tf32(a);
    q1h[idx] = ah;
    q1l[idx] = f2tf32(a - __uint_as_float(ah));
    float b = a + p;                       // k1 = q1 + pe (source bug kept)
    uint32_t bh = f2tf32(b);
    k1h[idx] = bh;
    k1l[idx] = f2tf32(b - __uint_as_float(bh));
}

// generic fp32 -> tf32 hi (+ optional lo) converter
__global__ void cvt_kernel(const float* __restrict__ in,
                           uint32_t* __restrict__ hi, uint32_t* __restrict__ lo, int n) {
    int i = blockIdx.x * blockDim.x + threadIdx.x;
    if (i >= n) return;
    float x = in[i];
    uint32_t h = f2tf32(x);
    hi[i] = h;
    if (lo) lo[i] = f2tf32(x - __uint_as_float(h));
}

// ---------------- column max over q ------------------------------------------
__global__ __launch_bounds__(256) void colmax_kernel(const float* __restrict__ S,
                                                     float* __restrict__ cmax) {
    int k = blockIdx.x * blockDim.x + threadIdx.x;
    int z = blockIdx.y;
    const float* Sp = S + (long)z * T_ * T_ + k;
    float m = -INFINITY;
    #pragma unroll 4
    for (int q = 0; q < T_; q++) m = fmaxf(m, Sp[(long)q * T_]);
    cmax[(long)z * T_ + k] = m;
}

// -------- row softmax of (s - colmax), * qmask; writes tf32 bits in place ----
__global__ __launch_bounds__(256) void softmax_kernel(float* __restrict__ S,
                                                      const float* __restrict__ cmax,
                                                      const int* __restrict__ qmasks) {
    __shared__ float sh[8];
    __shared__ float bc;
    int q = blockIdx.x;
    int z = blockIdx.y;
    int b = z % B_;
    float* row = S + (long)z * T_ * T_ + (long)q * T_;
    const float* cm = cmax + (long)z * T_;
    int tid = threadIdx.x;

    float x0 = row[tid]       - cm[tid];
    float x1 = row[tid + 256] - cm[tid + 256];

    float v = fmaxf(x0, x1);
    #pragma unroll
    for (int o = 16; o; o >>= 1) v = fmaxf(v, __shfl_xor_sync(0xffffffffu, v, o));
    if ((tid & 31) == 0) sh[tid >> 5] = v;
    __syncthreads();
    if (tid == 0) {
        float m = sh[0];
        #pragma unroll
        for (int i = 1; i < 8; i++) m = fmaxf(m, sh[i]);
        bc = m;
    }
    __syncthreads();
    float m = bc;

    float e0 = expf(x0 - m), e1 = expf(x1 - m);
    v = e0 + e1;
    #pragma unroll
    for (int o = 16; o; o >>= 1) v += __shfl_xor_sync(0xffffffffu, v, o);
    __syncthreads();
    if ((tid & 31) == 0) sh[tid >> 5] = v;
    __syncthreads();
    if (tid == 0) {
        float s = 0.f;
        #pragma unroll
        for (int i = 0; i < 8; i++) s += sh[i];
        bc = s;
    }
    __syncthreads();

    float qm  = (q < qmasks[b]) ? 1.f : 0.f;
    float inv = qm / bc;
    uint32_t* rowu = (uint32_t*)row;
    rowu[tid]       = f2tf32(e0 * inv);
    rowu[tid + 256] = f2tf32(e1 * inv);
}

// ---------------- launch -----------------------------------------------------
extern "C" void kernel_launch(void* const* d_in, const int* in_sizes, int n_in,
                              void* d_out, int out_size) {
    const float* queries = (const float*)d_in[0];
    const int*   qmasks  = (const int*)d_in[2];
    const float* W_Q = (const float*)d_in[4];
    const float* W_K = (const float*)d_in[5];
    const float* W_V = (const float*)d_in[6];
    const float* fw1 = (const float*)d_in[7];
    const float* fw2 = (const float*)d_in[8];
    float* out = (float*)d_out;

    float *pe, *q1f, *S, *cmax, *R;
    uint32_t *q1h, *q1l, *k1h, *k1l, *Qh, *Ql, *Kh, *Kl, *Vh, *Rh, *Hd;
    uint32_t *wqh, *wql, *wkh, *wkl, *wvh, *f1h, *f2h;
    cudaGetSymbolAddress((void**)&pe,  g_pe);
    cudaGetSymbolAddress((void**)&q1f, g_q1);
    cudaGetSymbolAddress((void**)&q1h, g_q1h);
    cudaGetSymbolAddress((void**)&q1l, g_q1l);
    cudaGetSymbolAddress((void**)&k1h, g_k1h);
    cudaGetSymbolAddress((void**)&k1l, g_k1l);
    cudaGetSymbolAddress((void**)&Qh,  g_Qh);
    cudaGetSymbolAddress((void**)&Ql,  g_Ql);
    cudaGetSymbolAddress((void**)&Kh,  g_Kh);
    cudaGetSymbolAddress((void**)&Kl,  g_Kl);
    cudaGetSymbolAddress((void**)&Vh,  g_Vh);
    cudaGetSymbolAddress((void**)&S,   g_S);
    cudaGetSymbolAddress((void**)&cmax, g_cmax);
    cudaGetSymbolAddress((void**)&R,   g_R);
    cudaGetSymbolAddress((void**)&Rh,  g_Rh);
    cudaGetSymbolAddress((void**)&Hd,  g_H);
    cudaGetSymbolAddress((void**)&wqh, g_wqh);
    cudaGetSymbolAddress((void**)&wql, g_wql);
    cudaGetSymbolAddress((void**)&wkh, g_wkh);
    cudaGetSymbolAddress((void**)&wkl, g_wkl);
    cudaGetSymbolAddress((void**)&wvh, g_wvh);
    cudaGetSymbolAddress((void**)&f1h, g_f1h);
    cudaGetSymbolAddress((void**)&f2h, g_f2h);

    const long TD = (long)T_ * D_;
    const long TT = (long)T_ * T_;

    constexpr int SM_P128 = smem3(128, false, false);  // 107520
    constexpr int SM_P64  = smem3(64,  false, false);  // 82944
    constexpr int SM_S0   = smem3(128, false, true);   // 113664
    constexpr int SM_S1   = smem3(128, true,  true);   // 122880

    cudaFuncSetAttribute(mma3<128, false, true,  2>, cudaFuncAttributeMaxDynamicSharedMemorySize, SM_S0);
    cudaFuncSetAttribute(mma3<128, true,  true,  0>, cudaFuncAttributeMaxDynamicSharedMemorySize, SM_S1);
    cudaFuncSetAttribute(mma3<128, false, false, 1>, cudaFuncAttributeMaxDynamicSharedMemorySize, SM_P128);
    cudaFuncSetAttribute(mma3<128, false, false, 0>, cudaFuncAttributeMaxDynamicSharedMemorySize, SM_P128);
    cudaFuncSetAttribute(mma3<64,  false, false, 3>, cudaFuncAttributeMaxDynamicSharedMemorySize, SM_P64);

    // 1) posenc + operand conversions
    pe_kernel<<<(T_ * D_ + 255) / 256, 256>>>(pe);
    addpe2_kernel<<<(B_ * T_ * D_) / 256, 256>>>(queries, pe, q1f, q1h, q1l, k1h, k1l);
    cvt_kernel<<<(D_ * D_ + 255) / 256, 256>>>(W_Q, wqh, wql, D_ * D_);
    cvt_kernel<<<(D_ * D_ + 255) / 256, 256>>>(W_K, wkh, wkl, D_ * D_);
    cvt_kernel<<<(D_ * D_ + 255) / 256, 256>>>(W_V, wvh, nullptr, D_ * D_);
    cvt_kernel<<<(D_ * FF_ + 255) / 256, 256>>>(fw1, f1h, nullptr, D_ * FF_);
    cvt_kernel<<<(FF_ * D_ + 255) / 256, 256>>>(fw2, f2h, nullptr, FF_ * D_);

    // 2) Q/K projections (3xTF32 split) -> hi+lo outputs
    {
        dim3 g(D_ / 128, (B_ * T_) / 128, 1);
        mma3<128, false, true, 2><<<g, 256, SM_S0>>>(
            q1h, q1l, 0, 0, D_, wqh, wql, 0, 0, D_,
            nullptr, Qh, Ql, 0, 0, D_, nullptr, 0, 0, 0, 1, D_, 1.f, 0);
        mma3<128, false, true, 2><<<g, 256, SM_S0>>>(
            k1h, k1l, 0, 0, D_, wkh, wkl, 0, 0, D_,
            nullptr, Kh, Kl, 0, 0, D_, nullptr, 0, 0, 0, 1, D_, 1.f, 0);
    }

    // 3) V projection: V = Kp @ W_V (bug kept) -> hi output
    {
        dim3 g(D_ / 128, (B_ * T_) / 128, 1);
        mma3<128, false, false, 1><<<g, 256, SM_P128>>>(
            Kh, nullptr, 0, 0, D_, wvh, nullptr, 0, 0, D_,
            nullptr, Vh, nullptr, 0, 0, D_, nullptr, 0, 0, 0, 1, D_, 1.f, 0);
    }

    // 4) scores (3xTF32 split, B = K head-slices [N][K]) -> fp32
    {
        dim3 g(T_ / 128, T_ / 128, HB_);
        mma3<128, true, true, 0><<<g, 256, SM_S1>>>(
            Qh, Ql, DH_, TD, D_,
            Kh, Kl, DH_, TD, D_,
            S, nullptr, nullptr, (long)B_ * TT, TT, T_,
            nullptr, 0, 0, 0,
            B_, DH_, 0.125f, 0);
    }

    // 5) colmax + softmax (softmax leaves tf32 bits in S)
    colmax_kernel<<<dim3(T_ / 256, HB_), 256>>>(S, cmax);
    softmax_kernel<<<dim3(T_, HB_), 256>>>(S, cmax, qmasks);

    // 6) AV: R = attn @ Vh + q1 residual -> fp32 + hi
    {
        dim3 g(1, T_ / 128, HB_);
        mma3<64, false, false, 3><<<g, 256, SM_P64>>>(
            (const uint32_t*)S, nullptr, (long)B_ * TT, TT, T_,
            Vh, nullptr, DH_, TD, D_,
            R, Rh, nullptr, DH_, TD, D_,
            q1f, DH_, TD, D_,
            B_, T_, 1.f, 0);
    }

    // 7) FFN1: hidden = relu(R @ fw1) -> hi
    {
        dim3 g(FF_ / 128, (B_ * T_) / 128, 1);
        mma3<128, false, false, 1><<<g, 256, SM_P128>>>(
            Rh, nullptr, 0, 0, D_, f1h, nullptr, 0, 0, FF_,
            nullptr, Hd, nullptr, 0, 0, FF_, nullptr, 0, 0, 0, 1, D_, 1.f, 1);
    }

    // 8) FFN2: out = R + hidden @ fw2 -> fp32
    {
        dim3 g(D_ / 128, (B_ * T_) / 128, 1);
        mma3<128, false, false, 0><<<g, 256, SM_P128>>>(
            Hd, nullptr, 0, 0, FF_, f2h, nullptr, 0, 0, D_,
            out, nullptr, nullptr, 0, 0, D_, R, 0, 0, D_, 1, FF_, 1.f, 0);
    }
}

// round 6
// speedup vs baseline: 2.3646x; 1.0832x over previous
#include <cuda_runtime.h>
#include <math.h>
#include <stdint.h>

// Problem constants
constexpr int B_  = 32;
constexpr int T_  = 512;
constexpr int D_  = 512;
constexpr int H_  = 8;
constexpr int DH_ = 64;
constexpr int HB_ = H_ * B_;        // 256
constexpr int FF_ = 4 * D_;         // 2048

// ---------------- scratch (static device globals; allocation-free) ----------
__device__ float    g_pe [T_ * D_];
__device__ float    g_q1 [B_ * T_ * D_];            // fp32 residual
__device__ uint32_t g_q1h[B_ * T_ * D_];
__device__ uint32_t g_q1l[B_ * T_ * D_];
__device__ uint32_t g_k1h[B_ * T_ * D_];
__device__ uint32_t g_k1l[B_ * T_ * D_];
__device__ uint32_t g_Qh [B_ * T_ * D_];
__device__ uint32_t g_Ql [B_ * T_ * D_];
__device__ uint32_t g_Kh [B_ * T_ * D_];
__device__ uint32_t g_Kl [B_ * T_ * D_];
__device__ uint32_t g_Vh [B_ * T_ * D_];
__device__ float    g_S  [(long)HB_ * T_ * T_];     // 256MB fp32 scores
__device__ float    g_cmax[HB_ * T_];
__device__ float    g_R  [B_ * T_ * D_];            // fp32 residual
__device__ uint32_t g_Rh [B_ * T_ * D_];
__device__ uint32_t g_H  [(long)B_ * T_ * FF_];     // hidden, tf32 bits, 128MB
// converted weights
__device__ uint32_t g_wqh[D_ * D_], g_wql[D_ * D_];
__device__ uint32_t g_wkh[D_ * D_], g_wkl[D_ * D_];
__device__ uint32_t g_wvh[D_ * D_];
__device__ uint32_t g_f1h[D_ * FF_];
__device__ uint32_t g_f2h[FF_ * D_];

// ---------------- helpers ---------------------------------------------------
__device__ __forceinline__ uint32_t f2tf32(float f) {
    uint32_t u;
    asm("cvt.rna.tf32.f32 %0, %1;" : "=r"(u) : "f"(f));
    return u;
}
__device__ __forceinline__ void mma16n8k8(float* c, const uint32_t* a, const uint32_t* b) {
    asm volatile(
        "mma.sync.aligned.m16n8k8.row.col.f32.tf32.tf32.f32 "
        "{%0,%1,%2,%3}, {%4,%5,%6,%7}, {%8,%9}, {%0,%1,%2,%3};"
        : "+f"(c[0]), "+f"(c[1]), "+f"(c[2]), "+f"(c[3])
        : "r"(a[0]), "r"(a[1]), "r"(a[2]), "r"(a[3]), "r"(b[0]), "r"(b[1]));
}
__device__ __forceinline__ uint32_t smem_u32(const void* p) {
    uint32_t a;
    asm("{ .reg .u64 t; cvta.to.shared.u64 t, %1; cvt.u32.u64 %0, t; }"
        : "=r"(a) : "l"(p));
    return a;
}
__device__ __forceinline__ void cpa16(uint32_t saddr, const void* g) {
    asm volatile("cp.async.ca.shared.global [%0], [%1], 16;"
                 :: "r"(saddr), "l"(g) : "memory");
}
#define CPA_COMMIT() asm volatile("cp.async.commit_group;" ::: "memory")
#define CPA_WAIT1()  asm volatile("cp.async.wait_group 1;" ::: "memory")
#define CPA_WAIT0()  asm volatile("cp.async.wait_group 0;" ::: "memory")

// monotone float atomic max (init must be -inf)
__device__ __forceinline__ void atomicMaxFloat(float* addr, float v) {
    if (v >= 0.f) atomicMax((int*)addr, __float_as_int(v));
    else          atomicMin((unsigned int*)addr, __float_as_uint(v));
}

// ============ tf32 mma.sync GEMM engine v3 (cp.async, preconverted) =========
// All operands are tf32 bit-images in gmem. A row-major (lda).
// B: TBB=0 -> [K][N]; TBB=1 -> [N][K]. SPLIT=1: 3xTF32 with hi/lo planes.
// OUT: 0 = fp32; 1 = tf32 hi; 2 = tf32 hi+lo.
// CM: epilogue column-max atomics into cmaxp (per z row of length ldc).
template<int BN, bool TBB, bool SPLIT, int OUT, bool CM>
__global__ void __launch_bounds__(256, SPLIT ? 1 : 2) mma3(
    const uint32_t* __restrict__ Ah_g, const uint32_t* __restrict__ Al_g,
    long sA1, long sA2, int lda,
    const uint32_t* __restrict__ Bh_g, const uint32_t* __restrict__ Bl_g,
    long sB1, long sB2, int ldb,
    float* Cf, uint32_t* Chi, uint32_t* Clo, long sC1, long sC2, int ldc,
    const float* __restrict__ Res, long sR1, long sR2, int ldres,
    float* cmaxp,
    int nb2, int K, float alpha, int relu)
{
    constexpr int BK   = SPLIT ? 16 : 32;
    constexpr int S    = 3;
    constexpr int AP   = BK + 4;
    constexpr int APL  = 128 * AP;
    constexpr int ASZ  = (SPLIT ? 2 : 1) * APL;
    constexpr int BPKN = BN + 8;
    constexpr int BPL  = TBB ? APL : BK * BPKN;
    constexpr int BSZ  = (SPLIT ? 2 : 1) * BPL;
    constexpr int ACH  = (128 * (BK / 4) * (SPLIT ? 2 : 1)) / 256;
    constexpr int BCH  = TBB ? ACH : ((BK * (BN / 4) * (SPLIT ? 2 : 1)) / 256);
    constexpr int nWN  = (BN == 128) ? 4 : 2;
    constexpr int nWM  = 8 / nWN;
    constexpr int WM   = 128 / nWM;
    constexpr int WN   = BN / nWN;
    constexpr int MT   = WM / 16;
    constexpr int NT   = WN / 8;

    extern __shared__ uint32_t sm[];
    const uint32_t sbase = smem_u32(sm);

    int z  = blockIdx.z;
    int i1 = z / nb2, i2 = z % nb2;
    Ah_g += i1 * sA1 + i2 * sA2;
    if (SPLIT) Al_g += i1 * sA1 + i2 * sA2;
    Bh_g += i1 * sB1 + i2 * sB2;
    if (SPLIT) Bl_g += i1 * sB1 + i2 * sB2;
    if (OUT == 0) Cf  += i1 * sC1 + i2 * sC2;
    if (OUT >= 1) Chi += i1 * sC1 + i2 * sC2;
    if (OUT == 2) Clo += i1 * sC1 + i2 * sC2;
    if (Res) Res += i1 * sR1 + i2 * sR2;
    if (CM)  cmaxp += (long)z * ldc;

    const int tid  = threadIdx.x;
    const int lane = tid & 31;
    const int wid  = tid >> 5;
    const int warp_m = wid % nWM;
    const int warp_n = wid / nWM;
    const int row0 = blockIdx.y * 128;
    const int col0 = blockIdx.x * BN;
    const int frow = lane >> 2, fcol = lane & 3;

    float acc[MT][NT][4];
    #pragma unroll
    for (int i = 0; i < MT; i++)
        #pragma unroll
        for (int j = 0; j < NT; j++)
            #pragma unroll
            for (int q = 0; q < 4; q++) acc[i][j][q] = 0.f;

    auto load_stage = [&](int st, int k0) {
        uint32_t sA = sbase + (uint32_t)(st * ASZ) * 4;
        #pragma unroll
        for (int i = 0; i < ACH; i++) {
            int idx = i * 256 + tid;
            int plane = SPLIT ? (idx >= 128 * (BK / 4) ? 1 : 0) : 0;
            int rem = idx - plane * 128 * (BK / 4);
            int row = rem / (BK / 4), c = rem % (BK / 4);
            const uint32_t* g = (plane ? Al_g : Ah_g)
                              + (long)(row0 + row) * lda + k0 + c * 4;
            cpa16(sA + (uint32_t)(plane * APL + row * AP + c * 4) * 4, g);
        }
        uint32_t sB = sbase + (uint32_t)(S * ASZ + st * BSZ) * 4;
        if (TBB) {
            #pragma unroll
            for (int i = 0; i < BCH; i++) {
                int idx = i * 256 + tid;
                int plane = SPLIT ? (idx >= 128 * (BK / 4) ? 1 : 0) : 0;
                int rem = idx - plane * 128 * (BK / 4);
                int row = rem / (BK / 4), c = rem % (BK / 4);
                const uint32_t* g = (plane ? Bl_g : Bh_g)
                                  + (long)(col0 + row) * ldb + k0 + c * 4;
                cpa16(sB + (uint32_t)(plane * BPL + row * AP + c * 4) * 4, g);
            }
        } else {
            #pragma unroll
            for (int i = 0; i < BCH; i++) {
                int idx = i * 256 + tid;
                int plane = SPLIT ? (idx >= BK * (BN / 4) ? 1 : 0) : 0;
                int rem = idx - plane * BK * (BN / 4);
                int row = rem / (BN / 4), c = rem % (BN / 4);
                const uint32_t* g = (plane ? Bl_g : Bh_g)
                                  + (long)(k0 + row) * ldb + col0 + c * 4;
                cpa16(sB + (uint32_t)(plane * BPL + row * BPKN + c * 4) * 4, g);
            }
        }
    };

    auto compute = [&](int st) {
        const uint32_t* As_h = sm + st * ASZ;
        const uint32_t* As_l = As_h + APL;
        const uint32_t* Bs_h = sm + S * ASZ + st * BSZ;
        const uint32_t* Bs_l = Bs_h + BPL;
        #pragma unroll
        for (int ks = 0; ks < BK / 8; ks++) {
            const int kk = ks * 8;
            uint32_t ah[MT][4], bh[NT][2];
            uint32_t al[MT][4], bl[NT][2];
            #pragma unroll
            for (int i = 0; i < MT; i++) {
                int r = warp_m * WM + i * 16 + frow;
                int c = kk + fcol;
                ah[i][0] = As_h[r * AP + c];
                ah[i][1] = As_h[(r + 8) * AP + c];
                ah[i][2] = As_h[r * AP + c + 4];
                ah[i][3] = As_h[(r + 8) * AP + c + 4];
                if (SPLIT) {
                    al[i][0] = As_l[r * AP + c];
                    al[i][1] = As_l[(r + 8) * AP + c];
                    al[i][2] = As_l[r * AP + c + 4];
                    al[i][3] = As_l[(r + 8) * AP + c + 4];
                }
            }
            #pragma unroll
            for (int j = 0; j < NT; j++) {
                int n = warp_n * WN + j * 8 + frow;
                if (TBB) {
                    bh[j][0] = Bs_h[n * AP + kk + fcol];
                    bh[j][1] = Bs_h[n * AP + kk + 4 + fcol];
                    if (SPLIT) {
                        bl[j][0] = Bs_l[n * AP + kk + fcol];
                        bl[j][1] = Bs_l[n * AP + kk + 4 + fcol];
                    }
                } else {
                    bh[j][0] = Bs_h[(kk + fcol) * BPKN + n];
                    bh[j][1] = Bs_h[(kk + 4 + fcol) * BPKN + n];
                    if (SPLIT) {
                        bl[j][0] = Bs_l[(kk + fcol) * BPKN + n];
                        bl[j][1] = Bs_l[(kk + 4 + fcol) * BPKN + n];
                    }
                }
            }
            #pragma unroll
            for (int i = 0; i < MT; i++)
                #pragma unroll
                for (int j = 0; j < NT; j++) {
                    mma16n8k8(acc[i][j], ah[i], bh[j]);
                    if (SPLIT) {
                        mma16n8k8(acc[i][j], ah[i], bl[j]);
                        mma16n8k8(acc[i][j], al[i], bh[j]);
                    }
                }
        }
    };

    const int NTL = K / BK;
    load_stage(0, 0);       CPA_COMMIT();
    load_stage(1, BK);      CPA_COMMIT();

    for (int kt = 0; kt < NTL; kt++) {
        CPA_WAIT1();
        __syncthreads();
        if (kt + 2 < NTL) load_stage((kt + 2) % S, (kt + 2) * BK);
        CPA_COMMIT();
        compute(kt % S);
    }

    // epilogue
    float colm[NT][2];
    if (CM) {
        #pragma unroll
        for (int j = 0; j < NT; j++) { colm[j][0] = -INFINITY; colm[j][1] = -INFINITY; }
    }
    #pragma unroll
    for (int i = 0; i < MT; i++) {
        #pragma unroll
        for (int j = 0; j < NT; j++) {
            int r = row0 + warp_m * WM + i * 16 + frow;
            int c = col0 + warp_n * WN + j * 8 + 2 * fcol;
            #pragma unroll
            for (int h = 0; h < 2; h++) {
                long rr = r + h * 8;
                float v0 = acc[i][j][2 * h] * alpha;
                float v1 = acc[i][j][2 * h + 1] * alpha;
                if (Res) {
                    v0 += Res[rr * (long)ldres + c];
                    v1 += Res[rr * (long)ldres + c + 1];
                }
                if (relu) { v0 = fmaxf(v0, 0.f); v1 = fmaxf(v1, 0.f); }
                if (CM) {
                    colm[j][0] = fmaxf(colm[j][0], v0);
                    colm[j][1] = fmaxf(colm[j][1], v1);
                }
                if (OUT == 0)
                    *(float2*)&Cf[rr * (long)ldc + c] = make_float2(v0, v1);
                if (OUT >= 1) {
                    uint32_t h0 = f2tf32(v0), h1 = f2tf32(v1);
                    uint2 hv; hv.x = h0; hv.y = h1;
                    *(uint2*)&Chi[rr * (long)ldc + c] = hv;
                    if (OUT == 2) {
                        uint2 lv;
                        lv.x = f2tf32(v0 - __uint_as_float(h0));
                        lv.y = f2tf32(v1 - __uint_as_float(h1));
                        *(uint2*)&Clo[rr * (long)ldc + c] = lv;
                    }
                }
            }
        }
    }
    if (CM) {
        #pragma unroll
        for (int j = 0; j < NT; j++) {
            #pragma unroll
            for (int s = 4; s <= 16; s <<= 1) {
                colm[j][0] = fmaxf(colm[j][0], __shfl_xor_sync(0xffffffffu, colm[j][0], s));
                colm[j][1] = fmaxf(colm[j][1], __shfl_xor_sync(0xffffffffu, colm[j][1], s));
            }
        }
        if (frow == 0) {
            #pragma unroll
            for (int j = 0; j < NT; j++) {
                int c = col0 + warp_n * WN + j * 8 + 2 * fcol;
                atomicMaxFloat(&cmaxp[c],     colm[j][0]);
                atomicMaxFloat(&cmaxp[c + 1], colm[j][1]);
            }
        }
    }
}

constexpr int smem3(int BN, bool TBB, bool SPLIT) {
    int BK = SPLIT ? 16 : 32, AP = BK + 4;
    int APL = 128 * AP, ASZ = (SPLIT ? 2 : 1) * APL;
    int BPL = TBB ? APL : BK * (BN + 8);
    int BSZ = (SPLIT ? 2 : 1) * BPL;
    return 4 * 3 * (ASZ + BSZ);
}

// ============ fused softmax + AV kernel ======================================
// grid (T/128, HB), 256 threads. Two-pass over S rows; MMA against Vh tiles.
constexpr int FS_PP = 68;                      // p-tile pitch (u32)
constexpr int FS_VP = 72;                      // V-tile pitch (u32)
constexpr int FS_PB = 0;                       // 2 * 128*68
constexpr int FS_VB = FS_PB + 2 * 128 * FS_PP; // 2 * 64*72
constexpr int FS_CM = FS_VB + 2 * 64 * FS_VP;  // 512
constexpr int FS_MM = FS_CM + 512;             // 128
constexpr int FS_SS = FS_MM + 128;             // 128
constexpr int FS_TOT_U32 = FS_SS + 128;
constexpr int FS_SMEM = FS_TOT_U32 * 4;        // 109,568 B

__global__ __launch_bounds__(256) void fsav_kernel(
    const float* __restrict__ S,
    const float* __restrict__ cmax,
    const uint32_t* __restrict__ Vh,
    const float* __restrict__ q1f,
    const int* __restrict__ qmasks,
    float* __restrict__ Rf, uint32_t* __restrict__ Rh)
{
    extern __shared__ uint32_t fs[];
    uint32_t* pb = fs + FS_PB;
    uint32_t* vb = fs + FS_VB;
    float* cm  = (float*)(fs + FS_CM);
    float* smM = (float*)(fs + FS_MM);
    float* smS = (float*)(fs + FS_SS);
    const uint32_t sbase = smem_u32(fs);

    const int tid = threadIdx.x, lane = tid & 31, wid = tid >> 5;
    const int q0 = blockIdx.x * 128;
    const int z  = blockIdx.y;
    const int hh = z / B_, b = z % B_;
    const float*    Sz = S + (long)z * T_ * T_;
    const uint32_t* Vz = Vh + (long)b * T_ * D_ + hh * DH_;
    const float*    Qz = q1f + (long)b * T_ * D_ + hh * DH_;
    float*    Rfz = Rf + (long)b * T_ * D_ + hh * DH_;
    uint32_t* Rhz = Rh + (long)b * T_ * D_ + hh * DH_;
    const int qlim = qmasks[b];

    cm[tid]       = cmax[z * T_ + tid];
    cm[tid + 256] = cmax[z * T_ + tid + 256];
    __syncthreads();

    // ---- phase 1: per-row max & sum (one warp per row) ----
    for (int it = 0; it < 16; it++) {
        int r = it * 8 + wid;
        const float* Srow = Sz + (long)(q0 + r) * T_;
        float x[16];
        #pragma unroll
        for (int seg = 0; seg < 4; seg++) {
            float4 v = *(const float4*)(Srow + seg * 128 + lane * 4);
            int c = seg * 128 + lane * 4;
            x[seg * 4 + 0] = v.x - cm[c + 0];
            x[seg * 4 + 1] = v.y - cm[c + 1];
            x[seg * 4 + 2] = v.z - cm[c + 2];
            x[seg * 4 + 3] = v.w - cm[c + 3];
        }
        float m = x[0];
        #pragma unroll
        for (int j = 1; j < 16; j++) m = fmaxf(m, x[j]);
        #pragma unroll
        for (int o = 16; o; o >>= 1) m = fmaxf(m, __shfl_xor_sync(0xffffffffu, m, o));
        float s = 0.f;
        #pragma unroll
        for (int j = 0; j < 16; j++) s += expf(x[j] - m);
        #pragma unroll
        for (int o = 16; o; o >>= 1) s += __shfl_xor_sync(0xffffffffu, s, o);
        if (lane == 0) { smM[r] = m; smS[r] = s; }
    }
    __syncthreads();

    // ---- phase 2: stream k-tiles of 64, regenerate p as tf32, MMA with V ----
    // warp layout: nWM=4, nWN=2 -> WM=32, WN=32, MT=2, NT=4
    const int warp_m = wid & 3, warp_n = wid >> 2;
    const int frow = lane >> 2, fcol = lane & 3;

    float acc[2][4][4];
    #pragma unroll
    for (int i = 0; i < 2; i++)
        #pragma unroll
        for (int j = 0; j < 4; j++)
            #pragma unroll
            for (int q = 0; q < 4; q++) acc[i][j][q] = 0.f;

    auto loadV = [&](int buf, int k0) {
        #pragma unroll
        for (int i = 0; i < 4; i++) {
            int row = i * 16 + (tid >> 4);
            int c4 = (tid & 15) * 4;
            cpa16(sbase + (uint32_t)(FS_VB + buf * 64 * FS_VP + row * FS_VP + c4) * 4,
                  Vz + (long)(k0 + row) * D_ + c4);
        }
    };
    auto genP = [&](int buf, int k0) {
        uint32_t* pt = pb + buf * 128 * FS_PP;
        #pragma unroll
        for (int pass = 0; pass < 8; pass++) {
            int r = pass * 16 + (tid >> 4);
            int c4 = (tid & 15) * 4;
            float4 v = *(const float4*)(Sz + (long)(q0 + r) * T_ + k0 + c4);
            float mm = smM[r];
            uint4 o;
            o.x = f2tf32(expf(v.x - cm[k0 + c4 + 0] - mm));
            o.y = f2tf32(expf(v.y - cm[k0 + c4 + 1] - mm));
            o.z = f2tf32(expf(v.z - cm[k0 + c4 + 2] - mm));
            o.w = f2tf32(expf(v.w - cm[k0 + c4 + 3] - mm));
            *(uint4*)&pt[r * FS_PP + c4] = o;
        }
    };

    loadV(0, 0); CPA_COMMIT();

    for (int kt = 0; kt < 8; kt++) {
        int buf = kt & 1;
        genP(buf, kt * 64);
        CPA_WAIT0();
        __syncthreads();
        if (kt + 1 < 8) { loadV(buf ^ 1, (kt + 1) * 64); CPA_COMMIT(); }
        const uint32_t* pt = pb + buf * 128 * FS_PP;
        const uint32_t* vt = vb + buf * 64 * FS_VP;
        #pragma unroll
        for (int ks = 0; ks < 8; ks++) {
            const int kk = ks * 8;
            uint32_t af[2][4], bf[4][2];
            #pragma unroll
            for (int i = 0; i < 2; i++) {
                int r = warp_m * 32 + i * 16 + frow;
                int c = kk + fcol;
                af[i][0] = pt[r * FS_PP + c];
                af[i][1] = pt[(r + 8) * FS_PP + c];
                af[i][2] = pt[r * FS_PP + c + 4];
                af[i][3] = pt[(r + 8) * FS_PP + c + 4];
            }
            #pragma unroll
            for (int j = 0; j < 4; j++) {
                int n = warp_n * 32 + j * 8 + frow;
                bf[j][0] = vt[(kk + fcol) * FS_VP + n];
                bf[j][1] = vt[(kk + 4 + fcol) * FS_VP + n];
            }
            #pragma unroll
            for (int i = 0; i < 2; i++)
                #pragma unroll
                for (int j = 0; j < 4; j++)
                    mma16n8k8(acc[i][j], af[i], bf[j]);
        }
        __syncthreads();
    }

    // ---- epilogue: scale by qmask/sum, add residual, write fp32 + tf32 ----
    #pragma unroll
    for (int i = 0; i < 2; i++) {
        #pragma unroll
        for (int j = 0; j < 4; j++) {
            int rloc = warp_m * 32 + i * 16 + frow;
            int c = warp_n * 32 + j * 8 + 2 * fcol;
            #pragma unroll
            for (int h = 0; h < 2; h++) {
                int rr = rloc + h * 8;
                float inv = ((q0 + rr) < qlim ? 1.f : 0.f) / smS[rr];
                long off = (long)(q0 + rr) * D_ + c;
                float v0 = acc[i][j][2 * h] * inv + Qz[off];
                float v1 = acc[i][j][2 * h + 1] * inv + Qz[off + 1];
                *(float2*)&Rfz[off] = make_float2(v0, v1);
                uint2 hv; hv.x = f2tf32(v0); hv.y = f2tf32(v1);
                *(uint2*)&Rhz[off] = hv;
            }
        }
    }
}

// ---------------- positional encoding (fp64 to match numpy) -----------------
__global__ void pe_kernel(float* __restrict__ pe) {
    int idx = blockIdx.x * blockDim.x + threadIdx.x;
    if (idx >= T_ * D_) return;
    int t = idx / D_;
    int d = idx % D_;
    double ang = (double)t * exp(-(2.0 * (double)d / (double)D_) * log(10000.0));
    double v = (d & 1) ? cos(ang) : sin(ang);
    pe[idx] = (float)(v * sqrt((double)D_));
}

__global__ void addpe2_kernel(const float* __restrict__ q, const float* __restrict__ pe,
                              float* __restrict__ q1f,
                              uint32_t* __restrict__ q1h, uint32_t* __restrict__ q1l,
                              uint32_t* __restrict__ k1h, uint32_t* __restrict__ k1l) {
    long idx = (long)blockIdx.x * blockDim.x + threadIdx.x;
    long td = idx % ((long)T_ * D_);
    float p = pe[td];
    float a = q[idx] + p;
    q1f[idx] = a;
    uint32_t ah = f2tf32(a);
    q1h[idx] = ah;
    q1l[idx] = f2tf32(a - __uint_as_float(ah));
    float bb = a + p;                      // k1 = q1 + pe (source bug kept)
    uint32_t bh = f2tf32(bb);
    k1h[idx] = bh;
    k1l[idx] = f2tf32(bb - __uint_as_float(bh));
}

__global__ void cvt_kernel(const float* __restrict__ in,
                           uint32_t* __restrict__ hi, uint32_t* __restrict__ lo, int n) {
    int i = blockIdx.x * blockDim.x + threadIdx.x;
    if (i >= n) return;
    float x = in[i];
    uint32_t h = f2tf32(x);
    hi[i] = h;
    if (lo) lo[i] = f2tf32(x - __uint_as_float(h));
}

__global__ void initmax_kernel(float* __restrict__ p, int n) {
    int i = blockIdx.x * blockDim.x + threadIdx.x;
    if (i < n) p[i] = -INFINITY;
}

// ---------------- launch -----------------------------------------------------
extern "C" void kernel_launch(void* const* d_in, const int* in_sizes, int n_in,
                              void* d_out, int out_size) {
    const float* queries = (const float*)d_in[0];
    const int*   qmasks  = (const int*)d_in[2];
    const float* W_Q = (const float*)d_in[4];
    const float* W_K = (const float*)d_in[5];
    const float* W_V = (const float*)d_in[6];
    const float* fw1 = (const float*)d_in[7];
    const float* fw2 = (const float*)d_in[8];
    float* out = (float*)d_out;

    float *pe, *q1f, *S, *cmax, *R;
    uint32_t *q1h, *q1l, *k1h, *k1l, *Qh, *Ql, *Kh, *Kl, *Vh, *Rh, *Hd;
    uint32_t *wqh, *wql, *wkh, *wkl, *wvh, *f1h, *f2h;
    cudaGetSymbolAddress((void**)&pe,  g_pe);
    cudaGetSymbolAddress((void**)&q1f, g_q1);
    cudaGetSymbolAddress((void**)&q1h, g_q1h);
    cudaGetSymbolAddress((void**)&q1l, g_q1l);
    cudaGetSymbolAddress((void**)&k1h, g_k1h);
    cudaGetSymbolAddress((void**)&k1l, g_k1l);
    cudaGetSymbolAddress((void**)&Qh,  g_Qh);
    cudaGetSymbolAddress((void**)&Ql,  g_Ql);
    cudaGetSymbolAddress((void**)&Kh,  g_Kh);
    cudaGetSymbolAddress((void**)&Kl,  g_Kl);
    cudaGetSymbolAddress((void**)&Vh,  g_Vh);
    cudaGetSymbolAddress((void**)&S,   g_S);
    cudaGetSymbolAddress((void**)&cmax, g_cmax);
    cudaGetSymbolAddress((void**)&R,   g_R);
    cudaGetSymbolAddress((void**)&Rh,  g_Rh);
    cudaGetSymbolAddress((void**)&Hd,  g_H);
    cudaGetSymbolAddress((void**)&wqh, g_wqh);
    cudaGetSymbolAddress((void**)&wql, g_wql);
    cudaGetSymbolAddress((void**)&wkh, g_wkh);
    cudaGetSymbolAddress((void**)&wkl, g_wkl);
    cudaGetSymbolAddress((void**)&wvh, g_wvh);
    cudaGetSymbolAddress((void**)&f1h, g_f1h);
    cudaGetSymbolAddress((void**)&f2h, g_f2h);

    const long TD = (long)T_ * D_;
    const long TT = (long)T_ * T_;

    constexpr int SM_P128 = smem3(128, false, false);
    constexpr int SM_S0   = smem3(128, false, true);
    constexpr int SM_S1   = smem3(128, true,  true);

    cudaFuncSetAttribute(mma3<128, false, true,  2, false>, cudaFuncAttributeMaxDynamicSharedMemorySize, SM_S0);
    cudaFuncSetAttribute(mma3<128, true,  true,  0, true>,  cudaFuncAttributeMaxDynamicSharedMemorySize, SM_S1);
    cudaFuncSetAttribute(mma3<128, false, false, 1, false>, cudaFuncAttributeMaxDynamicSharedMemorySize, SM_P128);
    cudaFuncSetAttribute(mma3<128, false, false, 0, false>, cudaFuncAttributeMaxDynamicSharedMemorySize, SM_P128);
    cudaFuncSetAttribute(fsav_kernel, cudaFuncAttributeMaxDynamicSharedMemorySize, FS_SMEM);

    // 1) posenc + operand conversions + cmax init
    pe_kernel<<<(T_ * D_ + 255) / 256, 256>>>(pe);
    addpe2_kernel<<<(B_ * T_ * D_) / 256, 256>>>(queries, pe, q1f, q1h, q1l, k1h, k1l);
    cvt_kernel<<<(D_ * D_ + 255) / 256, 256>>>(W_Q, wqh, wql, D_ * D_);
    cvt_kernel<<<(D_ * D_ + 255) / 256, 256>>>(W_K, wkh, wkl, D_ * D_);
    cvt_kernel<<<(D_ * D_ + 255) / 256, 256>>>(W_V, wvh, nullptr, D_ * D_);
    cvt_kernel<<<(D_ * FF_ + 255) / 256, 256>>>(fw1, f1h, nullptr, D_ * FF_);
    cvt_kernel<<<(FF_ * D_ + 255) / 256, 256>>>(fw2, f2h, nullptr, FF_ * D_);
    initmax_kernel<<<(HB_ * T_ + 255) / 256, 256>>>(cmax, HB_ * T_);

    // 2) Q/K projections (3xTF32 split) -> hi+lo
    {
        dim3 g(D_ / 128, (B_ * T_) / 128, 1);
        mma3<128, false, true, 2, false><<<g, 256, SM_S0>>>(
            q1h, q1l, 0, 0, D_, wqh, wql, 0, 0, D_,
            nullptr, Qh, Ql, 0, 0, D_, nullptr, 0, 0, 0, nullptr, 1, D_, 1.f, 0);
        mma3<128, false, true, 2, false><<<g, 256, SM_S0>>>(
            k1h, k1l, 0, 0, D_, wkh, wkl, 0, 0, D_,
            nullptr, Kh, Kl, 0, 0, D_, nullptr, 0, 0, 0, nullptr, 1, D_, 1.f, 0);
    }

    // 3) V projection: V = Kp @ W_V (bug kept) -> hi
    {
        dim3 g(D_ / 128, (B_ * T_) / 128, 1);
        mma3<128, false, false, 1, false><<<g, 256, SM_P128>>>(
            Kh, nullptr, 0, 0, D_, wvh, nullptr, 0, 0, D_,
            nullptr, Vh, nullptr, 0, 0, D_, nullptr, 0, 0, 0, nullptr, 1, D_, 1.f, 0);
    }

    // 4) scores (3xTF32 split) -> fp32 S + fused column-max atomics
    {
        dim3 g(T_ / 128, T_ / 128, HB_);
        mma3<128, true, true, 0, true><<<g, 256, SM_S1>>>(
            Qh, Ql, DH_, TD, D_,
            Kh, Kl, DH_, TD, D_,
            S, nullptr, nullptr, (long)B_ * TT, TT, T_,
            nullptr, 0, 0, 0, cmax,
            B_, DH_, 0.125f, 0);
    }

    // 5) fused softmax + AV: R = softmax(S - cmax) * qmask @ V + q1
    {
        dim3 g(T_ / 128, HB_);
        fsav_kernel<<<g, 256, FS_SMEM>>>(S, cmax, Vh, q1f, qmasks, R, Rh);
    }

    // 6) FFN1: hidden = relu(R @ fw1) -> hi
    {
        dim3 g(FF_ / 128, (B_ * T_) / 128, 1);
        mma3<128, false, false, 1, false><<<g, 256, SM_P128>>>(
            Rh, nullptr, 0, 0, D_, f1h, nullptr, 0, 0, FF_,
            nullptr, Hd, nullptr, 0, 0, FF_, nullptr, 0, 0, 0, nullptr, 1, D_, 1.f, 1);
    }

    // 7) FFN2: out = R + hidden @ fw2 -> fp32
    {
        dim3 g(D_ / 128, (B_ * T_) / 128, 1);
        mma3<128, false, false, 0, false><<<g, 256, SM_P128>>>(
            Hd, nullptr, 0, 0, FF_, f2h, nullptr, 0, 0, D_,
            out, nullptr, nullptr, 0, 0, D_, R, 0, 0, D_, nullptr, 1, FF_, 1.f, 0);
    }
}

// round 7
// speedup vs baseline: 4.3931x; 1.8578x over previous
#include <cuda_runtime.h>
#include <cuda_fp16.h>
#include <math.h>
#include <stdint.h>

// Problem constants
constexpr int B_  = 32;
constexpr int T_  = 512;
constexpr int D_  = 512;
constexpr int H_  = 8;
constexpr int DH_ = 64;
constexpr int HB_ = H_ * B_;        // 256
constexpr int FF_ = 4 * D_;         // 2048

// ---------------- scratch (static device globals; allocation-free) ----------
__device__ float  g_pe [T_ * D_];
__device__ float  g_q1 [B_ * T_ * D_];              // fp32 residual
__device__ __half g_q1h[B_ * T_ * D_];
__device__ __half g_q1l[B_ * T_ * D_];
__device__ __half g_k1h[B_ * T_ * D_];
__device__ __half g_k1l[B_ * T_ * D_];
__device__ __half g_Qh [B_ * T_ * D_];
__device__ __half g_Ql [B_ * T_ * D_];
__device__ __half g_Kh [B_ * T_ * D_];
__device__ __half g_Kl [B_ * T_ * D_];
__device__ __half g_Vh [B_ * T_ * D_];
__device__ float  g_S  [(long)HB_ * T_ * T_];       // 256MB fp32 scores
__device__ float  g_cmax[HB_ * T_];
__device__ float  g_R  [B_ * T_ * D_];              // fp32 residual
__device__ __half g_Rh [B_ * T_ * D_];
__device__ __half g_H  [(long)B_ * T_ * FF_];       // hidden (fp16), 64MB
// converted weights
__device__ __half g_wqh[D_ * D_], g_wql[D_ * D_];
__device__ __half g_wkh[D_ * D_], g_wkl[D_ * D_];
__device__ __half g_wvh[D_ * D_];
__device__ __half g_f1h[D_ * FF_];
__device__ __half g_f2h[FF_ * D_];

// ---------------- helpers ---------------------------------------------------
__device__ __forceinline__ void mma16n8k16(float* c, const uint32_t* a, const uint32_t* b) {
    asm volatile(
        "mma.sync.aligned.m16n8k16.row.col.f32.f16.f16.f32 "
        "{%0,%1,%2,%3}, {%4,%5,%6,%7}, {%8,%9}, {%0,%1,%2,%3};"
        : "+f"(c[0]), "+f"(c[1]), "+f"(c[2]), "+f"(c[3])
        : "r"(a[0]), "r"(a[1]), "r"(a[2]), "r"(a[3]), "r"(b[0]), "r"(b[1]));
}
__device__ __forceinline__ void ldsm_x4(uint32_t* r, uint32_t a) {
    asm volatile("ldmatrix.sync.aligned.m8n8.x4.shared.b16 {%0,%1,%2,%3}, [%4];"
        : "=r"(r[0]), "=r"(r[1]), "=r"(r[2]), "=r"(r[3]) : "r"(a));
}
__device__ __forceinline__ void ldsm_x2(uint32_t* r, uint32_t a) {
    asm volatile("ldmatrix.sync.aligned.m8n8.x2.shared.b16 {%0,%1}, [%2];"
        : "=r"(r[0]), "=r"(r[1]) : "r"(a));
}
__device__ __forceinline__ void ldsm_x2t(uint32_t* r, uint32_t a) {
    asm volatile("ldmatrix.sync.aligned.m8n8.x2.trans.shared.b16 {%0,%1}, [%2];"
        : "=r"(r[0]), "=r"(r[1]) : "r"(a));
}
__device__ __forceinline__ uint32_t smem_u32(const void* p) {
    uint32_t a;
    asm("{ .reg .u64 t; cvta.to.shared.u64 t, %1; cvt.u32.u64 %0, t; }"
        : "=r"(a) : "l"(p));
    return a;
}
__device__ __forceinline__ void cpa16(uint32_t saddr, const void* g) {
    asm volatile("cp.async.ca.shared.global [%0], [%1], 16;"
                 :: "r"(saddr), "l"(g) : "memory");
}
#define CPA_COMMIT() asm volatile("cp.async.commit_group;" ::: "memory")
#define CPA_WAIT1()  asm volatile("cp.async.wait_group 1;" ::: "memory")
#define CPA_WAIT0()  asm volatile("cp.async.wait_group 0;" ::: "memory")

__device__ __forceinline__ void atomicMaxFloat(float* addr, float v) {
    if (v >= 0.f) atomicMax((int*)addr, __float_as_int(v));
    else          atomicMin((unsigned int*)addr, __float_as_uint(v));
}

// ============ fp16 mma.sync GEMM engine v4 (ldmatrix + cp.async) ============
// Block tile 128x128, BK=32, 256 threads (8 warps: nWM=2, nWN=4; WM=64, WN=32).
// A row-major [M][K] fp16. B: TBB=0 -> [K][N]; TBB=1 -> [N][K].
// SPLIT: hi/lo planes, 3 MMAs (hi*hi + hi*lo + lo*hi).
// OUT: 0 = fp32; 1 = fp16 hi; 2 = fp16 hi+lo.  CM: fused column-max atomics.
template<bool TBB, bool SPLIT, int OUT, bool CM, int NS>
__global__ void __launch_bounds__(256, 2) mma4(
    const __half* __restrict__ Ah_g, const __half* __restrict__ Al_g,
    long sA1, long sA2, int lda,
    const __half* __restrict__ Bh_g, const __half* __restrict__ Bl_g,
    long sB1, long sB2, int ldb,
    float* Cf, __half* Chi, __half* Clo, long sC1, long sC2, int ldc,
    const float* __restrict__ Res, long sR1, long sR2, int ldres,
    float* cmaxp,
    int nb2, int K, float alpha, int relu)
{
    constexpr int BK  = 32;
    constexpr int AP  = 40;                 // A pitch (halves); 80B stride: conflict-free
    constexpr int APL = 128 * AP;           // 5120 halves per A plane
    constexpr int NSP = SPLIT ? 2 : 1;
    constexpr int ASZ = NSP * APL;
    constexpr int BP  = 136;                // [K][N] B pitch
    constexpr int BPL = TBB ? APL : BK * BP;
    constexpr int BSZ = NSP * BPL;
    constexpr int STG = ASZ + BSZ;          // halves per stage
    constexpr int MT  = 4;                  // 64/16
    constexpr int NT  = 4;                  // 32/8

    extern __shared__ __half smh[];
    const uint32_t sbase = smem_u32(smh);

    int z  = blockIdx.z;
    int i1 = z / nb2, i2 = z % nb2;
    Ah_g += i1 * sA1 + i2 * sA2;
    if (SPLIT) Al_g += i1 * sA1 + i2 * sA2;
    Bh_g += i1 * sB1 + i2 * sB2;
    if (SPLIT) Bl_g += i1 * sB1 + i2 * sB2;
    if (OUT == 0) Cf  += i1 * sC1 + i2 * sC2;
    if (OUT >= 1) Chi += i1 * sC1 + i2 * sC2;
    if (OUT == 2) Clo += i1 * sC1 + i2 * sC2;
    if (Res) Res += i1 * sR1 + i2 * sR2;
    if (CM)  cmaxp += (long)z * ldc;

    const int tid  = threadIdx.x;
    const int lane = tid & 31;
    const int wid  = tid >> 5;
    const int warp_m = wid & 1;
    const int warp_n = wid >> 1;
    const int row0 = blockIdx.y * 128;
    const int col0 = blockIdx.x * 128;
    const int frow = lane >> 2, fcol = lane & 3;

    float acc[MT][NT][4];
    #pragma unroll
    for (int i = 0; i < MT; i++)
        #pragma unroll
        for (int j = 0; j < NT; j++)
            #pragma unroll
            for (int q = 0; q < 4; q++) acc[i][j][q] = 0.f;

    // ---- stage loader: cp.async 16B chunks (8 halves) ----
    auto load_stage = [&](int st, int k0) {
        uint32_t sA = sbase + (uint32_t)(st * STG) * 2;
        #pragma unroll
        for (int i = 0; i < 2 * NSP; i++) {
            int idx = i * 256 + tid;           // 512 chunks per plane
            int plane = idx >> 9;
            int rem = idx & 511;
            int row = rem >> 2, c8 = (rem & 3) * 8;
            const __half* g = (SPLIT && plane ? Al_g : Ah_g)
                            + (long)(row0 + row) * lda + k0 + c8;
            cpa16(sA + (uint32_t)(plane * APL + row * AP + c8) * 2, g);
        }
        uint32_t sB = sbase + (uint32_t)(st * STG + ASZ) * 2;
        if (TBB) {
            #pragma unroll
            for (int i = 0; i < 2 * NSP; i++) {
                int idx = i * 256 + tid;
                int plane = idx >> 9;
                int rem = idx & 511;
                int row = rem >> 2, c8 = (rem & 3) * 8;
                const __half* g = (SPLIT && plane ? Bl_g : Bh_g)
                                + (long)(col0 + row) * ldb + k0 + c8;
                cpa16(sB + (uint32_t)(plane * APL + row * AP + c8) * 2, g);
            }
        } else {
            #pragma unroll
            for (int i = 0; i < 2 * NSP; i++) {
                int idx = i * 256 + tid;       // 32*16 = 512 chunks per plane
                int plane = idx >> 9;
                int rem = idx & 511;
                int row = rem >> 4, c8 = (rem & 15) * 8;
                const __half* g = (SPLIT && plane ? Bl_g : Bh_g)
                                + (long)(k0 + row) * ldb + col0 + c8;
                cpa16(sB + (uint32_t)(plane * BPL + row * BP + c8) * 2, g);
            }
        }
    };

    auto compute = [&](int st) {
        const uint32_t aB = sbase + (uint32_t)(st * STG) * 2;
        const uint32_t bB = aB + (uint32_t)ASZ * 2;
        #pragma unroll
        for (int ks = 0; ks < 2; ks++) {
            const int kk = ks * 16;
            uint32_t af[MT][4], bh[NT][2];
            #pragma unroll
            for (int i = 0; i < MT; i++)
                ldsm_x4(af[i], aB + (uint32_t)((warp_m * 64 + i * 16 + (lane & 15)) * AP
                                               + kk + (lane >> 4) * 8) * 2);
            #pragma unroll
            for (int j = 0; j < NT; j++) {
                if (TBB)
                    ldsm_x2(bh[j], bB + (uint32_t)((warp_n * 32 + j * 8 + (lane & 7)) * AP
                                                   + kk + ((lane >> 3) & 1) * 8) * 2);
                else
                    ldsm_x2t(bh[j], bB + (uint32_t)((kk + (lane & 15)) * BP
                                                    + warp_n * 32 + j * 8) * 2);
            }
            #pragma unroll
            for (int i = 0; i < MT; i++)
                #pragma unroll
                for (int j = 0; j < NT; j++)
                    mma16n8k16(acc[i][j], af[i], bh[j]);
            if (SPLIT) {
                uint32_t b2[NT][2];
                #pragma unroll
                for (int j = 0; j < NT; j++) {
                    if (TBB)
                        ldsm_x2(b2[j], bB + (uint32_t)(APL + (warp_n * 32 + j * 8 + (lane & 7)) * AP
                                                       + kk + ((lane >> 3) & 1) * 8) * 2);
                    else
                        ldsm_x2t(b2[j], bB + (uint32_t)(BPL + (kk + (lane & 15)) * BP
                                                        + warp_n * 32 + j * 8) * 2);
                }
                #pragma unroll
                for (int i = 0; i < MT; i++)
                    #pragma unroll
                    for (int j = 0; j < NT; j++)
                        mma16n8k16(acc[i][j], af[i], b2[j]);
                #pragma unroll
                for (int i = 0; i < MT; i++)   // overwrite af with A-lo
                    ldsm_x4(af[i], aB + (uint32_t)(APL + (warp_m * 64 + i * 16 + (lane & 15)) * AP
                                                   + kk + (lane >> 4) * 8) * 2);
                #pragma unroll
                for (int i = 0; i < MT; i++)
                    #pragma unroll
                    for (int j = 0; j < NT; j++)
                        mma16n8k16(acc[i][j], af[i], bh[j]);
            }
        }
    };

    const int NTL = K / BK;
    if (NS == 3) {
        load_stage(0, 0);   CPA_COMMIT();
        load_stage(1, BK);  CPA_COMMIT();
        for (int kt = 0; kt < NTL; kt++) {
            CPA_WAIT1();
            __syncthreads();
            if (kt + 2 < NTL) load_stage((kt + 2) % 3, (kt + 2) * BK);
            CPA_COMMIT();
            compute(kt % 3);
        }
    } else {  // NS == 2
        load_stage(0, 0);   CPA_COMMIT();
        for (int kt = 0; kt < NTL; kt++) {
            if (kt + 1 < NTL) load_stage((kt + 1) & 1, (kt + 1) * BK);
            CPA_COMMIT();
            CPA_WAIT1();
            __syncthreads();
            compute(kt & 1);
            __syncthreads();
        }
    }

    // ---- epilogue ----
    float colm[NT][2];
    if (CM) {
        #pragma unroll
        for (int j = 0; j < NT; j++) { colm[j][0] = -INFINITY; colm[j][1] = -INFINITY; }
    }
    #pragma unroll
    for (int i = 0; i < MT; i++) {
        #pragma unroll
        for (int j = 0; j < NT; j++) {
            int r = row0 + warp_m * 64 + i * 16 + frow;
            int c = col0 + warp_n * 32 + j * 8 + 2 * fcol;
            #pragma unroll
            for (int h = 0; h < 2; h++) {
                long rr = r + h * 8;
                float v0 = acc[i][j][2 * h] * alpha;
                float v1 = acc[i][j][2 * h + 1] * alpha;
                if (Res) {
                    v0 += Res[rr * (long)ldres + c];
                    v1 += Res[rr * (long)ldres + c + 1];
                }
                if (relu) { v0 = fmaxf(v0, 0.f); v1 = fmaxf(v1, 0.f); }
                if (CM) {
                    colm[j][0] = fmaxf(colm[j][0], v0);
                    colm[j][1] = fmaxf(colm[j][1], v1);
                }
                if (OUT == 0)
                    *(float2*)&Cf[rr * (long)ldc + c] = make_float2(v0, v1);
                if (OUT >= 1) {
                    __half h0 = __float2half_rn(v0), h1 = __float2half_rn(v1);
                    *(__half2*)&Chi[rr * (long)ldc + c] = __halves2half2(h0, h1);
                    if (OUT == 2) {
                        __half l0 = __float2half_rn(v0 - __half2float(h0));
                        __half l1 = __float2half_rn(v1 - __half2float(h1));
                        *(__half2*)&Clo[rr * (long)ldc + c] = __halves2half2(l0, l1);
                    }
                }
            }
        }
    }
    if (CM) {
        #pragma unroll
        for (int j = 0; j < NT; j++) {
            #pragma unroll
            for (int s = 4; s <= 16; s <<= 1) {
                colm[j][0] = fmaxf(colm[j][0], __shfl_xor_sync(0xffffffffu, colm[j][0], s));
                colm[j][1] = fmaxf(colm[j][1], __shfl_xor_sync(0xffffffffu, colm[j][1], s));
            }
        }
        if (frow == 0) {
            #pragma unroll
            for (int j = 0; j < NT; j++) {
                int c = col0 + warp_n * 32 + j * 8 + 2 * fcol;
                atomicMaxFloat(&cmaxp[c],     colm[j][0]);
                atomicMaxFloat(&cmaxp[c + 1], colm[j][1]);
            }
        }
    }
}

constexpr int smem4(bool TBB, bool SPLIT, int NS) {
    int APL = 128 * 40, NSP = SPLIT ? 2 : 1;
    int BPL = TBB ? APL : 32 * 136;
    return 2 * NS * NSP * (APL + BPL);
}

// ============ fused softmax + AV kernel (fp16 MMA) ===========================
// grid (T/128, HB), 256 threads. p tile [128][72] halves; V tile [64][72].
constexpr int FS_PB   = 0;
constexpr int FS_VB   = FS_PB + 2 * 128 * 72 * 2;      // 36864
constexpr int FS_CM   = FS_VB + 2 * 64 * 72 * 2;       // 55296
constexpr int FS_MM   = FS_CM + 512 * 4;               // 57344
constexpr int FS_SS   = FS_MM + 128 * 4;               // 57856
constexpr int FS_SMEM = FS_SS + 128 * 4;               // 58368

__global__ __launch_bounds__(256, 2) void fsav_kernel(
    const float* __restrict__ S,
    const float* __restrict__ cmax,
    const __half* __restrict__ Vh,
    const float* __restrict__ q1f,
    const int* __restrict__ qmasks,
    float* __restrict__ Rf, __half* __restrict__ Rh)
{
    extern __shared__ char fs[];
    float* cm  = (float*)(fs + FS_CM);
    float* smM = (float*)(fs + FS_MM);
    float* smS = (float*)(fs + FS_SS);
    const uint32_t sbase = smem_u32(fs);

    const int tid = threadIdx.x, lane = tid & 31, wid = tid >> 5;
    const int q0 = blockIdx.x * 128;
    const int z  = blockIdx.y;
    const int hh = z / B_, b = z % B_;
    const float*  Sz = S + (long)z * T_ * T_;
    const __half* Vz = Vh + (long)b * T_ * D_ + hh * DH_;
    const float*  Qz = q1f + (long)b * T_ * D_ + hh * DH_;
    float*  Rfz = Rf + (long)b * T_ * D_ + hh * DH_;
    __half* Rhz = Rh + (long)b * T_ * D_ + hh * DH_;
    const int qlim = qmasks[b];

    cm[tid]       = cmax[z * T_ + tid];
    cm[tid + 256] = cmax[z * T_ + tid + 256];
    __syncthreads();

    // ---- phase 1: per-row max & sum (one warp per row) ----
    for (int it = 0; it < 16; it++) {
        int r = it * 8 + wid;
        const float* Srow = Sz + (long)(q0 + r) * T_;
        float x[16];
        #pragma unroll
        for (int seg = 0; seg < 4; seg++) {
            float4 v = *(const float4*)(Srow + seg * 128 + lane * 4);
            int c = seg * 128 + lane * 4;
            x[seg * 4 + 0] = v.x - cm[c + 0];
            x[seg * 4 + 1] = v.y - cm[c + 1];
            x[seg * 4 + 2] = v.z - cm[c + 2];
            x[seg * 4 + 3] = v.w - cm[c + 3];
        }
        float m = x[0];
        #pragma unroll
        for (int j = 1; j < 16; j++) m = fmaxf(m, x[j]);
        #pragma unroll
        for (int o = 16; o; o >>= 1) m = fmaxf(m, __shfl_xor_sync(0xffffffffu, m, o));
        float s = 0.f;
        #pragma unroll
        for (int j = 0; j < 16; j++) s += expf(x[j] - m);
        #pragma unroll
        for (int o = 16; o; o >>= 1) s += __shfl_xor_sync(0xffffffffu, s, o);
        if (lane == 0) { smM[r] = m; smS[r] = s; }
    }
    __syncthreads();

    // ---- phase 2: stream k-tiles of 64: regenerate p (fp16), MMA with V ----
    const int warp_m = wid & 3, warp_n = wid >> 2;  // WM=32 (MT=2), WN=32 (NT=4)
    const int frow = lane >> 2, fcol = lane & 3;

    float acc[2][4][4];
    #pragma unroll
    for (int i = 0; i < 2; i++)
        #pragma unroll
        for (int j = 0; j < 4; j++)
            #pragma unroll
            for (int q = 0; q < 4; q++) acc[i][j][q] = 0.f;

    auto loadV = [&](int buf, int k0) {
        #pragma unroll
        for (int i = 0; i < 2; i++) {
            int idx = i * 256 + tid;         // 64*8 = 512 chunks
            int row = idx >> 3, c8 = (idx & 7) * 8;
            cpa16(sbase + (uint32_t)(FS_VB + (buf * 64 * 72 + row * 72 + c8) * 2),
                  Vz + (long)(k0 + row) * D_ + c8);
        }
    };
    auto genP = [&](int buf, int k0) {
        __half* pt = (__half*)(fs + FS_PB) + buf * 128 * 72;
        #pragma unroll
        for (int pass = 0; pass < 8; pass++) {
            int r = pass * 16 + (tid >> 4);
            int c4 = (tid & 15) * 4;
            float4 v = *(const float4*)(Sz + (long)(q0 + r) * T_ + k0 + c4);
            float mm = smM[r];
            __half2 p0 = __floats2half2_rn(expf(v.x - cm[k0 + c4 + 0] - mm),
                                           expf(v.y - cm[k0 + c4 + 1] - mm));
            __half2 p1 = __floats2half2_rn(expf(v.z - cm[k0 + c4 + 2] - mm),
                                           expf(v.w - cm[k0 + c4 + 3] - mm));
            *(__half2*)&pt[r * 72 + c4]     = p0;
            *(__half2*)&pt[r * 72 + c4 + 2] = p1;
        }
    };

    loadV(0, 0); CPA_COMMIT();

    for (int kt = 0; kt < 8; kt++) {
        int buf = kt & 1;
        genP(buf, kt * 64);
        CPA_WAIT0();
        __syncthreads();
        if (kt + 1 < 8) { loadV(buf ^ 1, (kt + 1) * 64); CPA_COMMIT(); }
        const uint32_t pB = sbase + (uint32_t)(FS_PB + buf * 128 * 72 * 2);
        const uint32_t vB = sbase + (uint32_t)(FS_VB + buf * 64 * 72 * 2);
        #pragma unroll
        for (int ks = 0; ks < 4; ks++) {
            const int kk = ks * 16;
            uint32_t af[2][4], bf[4][2];
            #pragma unroll
            for (int i = 0; i < 2; i++)
                ldsm_x4(af[i], pB + (uint32_t)((warp_m * 32 + i * 16 + (lane & 15)) * 72
                                               + kk + (lane >> 4) * 8) * 2);
            #pragma unroll
            for (int j = 0; j < 4; j++)
                ldsm_x2t(bf[j], vB + (uint32_t)((kk + (lane & 15)) * 72
                                                + warp_n * 32 + j * 8) * 2);
            #pragma unroll
            for (int i = 0; i < 2; i++)
                #pragma unroll
                for (int j = 0; j < 4; j++)
                    mma16n8k16(acc[i][j], af[i], bf[j]);
        }
        __syncthreads();
    }

    // ---- epilogue: scale by qmask/sum, add residual, write fp32 + fp16 ----
    #pragma unroll
    for (int i = 0; i < 2; i++) {
        #pragma unroll
        for (int j = 0; j < 4; j++) {
            int rloc = warp_m * 32 + i * 16 + frow;
            int c = warp_n * 32 + j * 8 + 2 * fcol;
            #pragma unroll
            for (int h = 0; h < 2; h++) {
                int rr = rloc + h * 8;
                float inv = ((q0 + rr) < qlim ? 1.f : 0.f) / smS[rr];
                long off = (long)(q0 + rr) * D_ + c;
                float v0 = acc[i][j][2 * h] * inv + Qz[off];
                float v1 = acc[i][j][2 * h + 1] * inv + Qz[off + 1];
                *(float2*)&Rfz[off] = make_float2(v0, v1);
                *(__half2*)&Rhz[off] = __floats2half2_rn(v0, v1);
            }
        }
    }
}

// ---------------- positional encoding (fp64 to match numpy) -----------------
__global__ void pe_kernel(float* __restrict__ pe) {
    int idx = blockIdx.x * blockDim.x + threadIdx.x;
    if (idx >= T_ * D_) return;
    int t = idx / D_;
    int d = idx % D_;
    double ang = (double)t * exp(-(2.0 * (double)d / (double)D_) * log(10000.0));
    double v = (d & 1) ? cos(ang) : sin(ang);
    pe[idx] = (float)(v * sqrt((double)D_));
}

__global__ void addpe2_kernel(const float* __restrict__ q, const float* __restrict__ pe,
                              float* __restrict__ q1f,
                              __half* __restrict__ q1h, __half* __restrict__ q1l,
                              __half* __restrict__ k1h, __half* __restrict__ k1l) {
    long idx = (long)blockIdx.x * blockDim.x + threadIdx.x;
    long td = idx % ((long)T_ * D_);
    float p = pe[td];
    float a = q[idx] + p;
    q1f[idx] = a;
    __half ah = __float2half_rn(a);
    q1h[idx] = ah;
    q1l[idx] = __float2half_rn(a - __half2float(ah));
    float bb = a + p;                      // k1 = q1 + pe (source bug kept)
    __half bh = __float2half_rn(bb);
    k1h[idx] = bh;
    k1l[idx] = __float2half_rn(bb - __half2float(bh));
}

__global__ void cvt_kernel(const float* __restrict__ in,
                           __half* __restrict__ hi, __half* __restrict__ lo, int n) {
    int i = blockIdx.x * blockDim.x + threadIdx.x;
    if (i >= n) return;
    float x = in[i];
    __half h = __float2half_rn(x);
    hi[i] = h;
    if (lo) lo[i] = __float2half_rn(x - __half2float(h));
}

__global__ void initmax_kernel(float* __restrict__ p, int n) {
    int i = blockIdx.x * blockDim.x + threadIdx.x;
    if (i < n) p[i] = -INFINITY;
}

// ---------------- launch -----------------------------------------------------
extern "C" void kernel_launch(void* const* d_in, const int* in_sizes, int n_in,
                              void* d_out, int out_size) {
    const float* queries = (const float*)d_in[0];
    const int*   qmasks  = (const int*)d_in[2];
    const float* W_Q = (const float*)d_in[4];
    const float* W_K = (const float*)d_in[5];
    const float* W_V = (const float*)d_in[6];
    const float* fw1 = (const float*)d_in[7];
    const float* fw2 = (const float*)d_in[8];
    float* out = (float*)d_out;

    float *pe, *q1f, *S, *cmax, *R;
    __half *q1h, *q1l, *k1h, *k1l, *Qh, *Ql, *Kh, *Kl, *Vh, *Rh, *Hd;
    __half *wqh, *wql, *wkh, *wkl, *wvh, *f1h, *f2h;
    cudaGetSymbolAddress((void**)&pe,  g_pe);
    cudaGetSymbolAddress((void**)&q1f, g_q1);
    cudaGetSymbolAddress((void**)&q1h, g_q1h);
    cudaGetSymbolAddress((void**)&q1l, g_q1l);
    cudaGetSymbolAddress((void**)&k1h, g_k1h);
    cudaGetSymbolAddress((void**)&k1l, g_k1l);
    cudaGetSymbolAddress((void**)&Qh,  g_Qh);
    cudaGetSymbolAddress((void**)&Ql,  g_Ql);
    cudaGetSymbolAddress((void**)&Kh,  g_Kh);
    cudaGetSymbolAddress((void**)&Kl,  g_Kl);
    cudaGetSymbolAddress((void**)&Vh,  g_Vh);
    cudaGetSymbolAddress((void**)&S,   g_S);
    cudaGetSymbolAddress((void**)&cmax, g_cmax);
    cudaGetSymbolAddress((void**)&R,   g_R);
    cudaGetSymbolAddress((void**)&Rh,  g_Rh);
    cudaGetSymbolAddress((void**)&Hd,  g_H);
    cudaGetSymbolAddress((void**)&wqh, g_wqh);
    cudaGetSymbolAddress((void**)&wql, g_wql);
    cudaGetSymbolAddress((void**)&wkh, g_wkh);
    cudaGetSymbolAddress((void**)&wkl, g_wkl);
    cudaGetSymbolAddress((void**)&wvh, g_wvh);
    cudaGetSymbolAddress((void**)&f1h, g_f1h);
    cudaGetSymbolAddress((void**)&f2h, g_f2h);

    const long TD = (long)T_ * D_;
    const long TT = (long)T_ * T_;

    constexpr int SM_PLAIN = smem4(false, false, 3);  // 56832
    constexpr int SM_SPL0  = smem4(false, true,  2);  // 75776
    constexpr int SM_SPL1  = smem4(true,  true,  2);  // 81920

    cudaFuncSetAttribute(mma4<false, true,  2, false, 2>, cudaFuncAttributeMaxDynamicSharedMemorySize, SM_SPL0);
    cudaFuncSetAttribute(mma4<true,  true,  0, true,  2>, cudaFuncAttributeMaxDynamicSharedMemorySize, SM_SPL1);
    cudaFuncSetAttribute(mma4<false, false, 1, false, 3>, cudaFuncAttributeMaxDynamicSharedMemorySize, SM_PLAIN);
    cudaFuncSetAttribute(mma4<false, false, 0, false, 3>, cudaFuncAttributeMaxDynamicSharedMemorySize, SM_PLAIN);
    cudaFuncSetAttribute(fsav_kernel, cudaFuncAttributeMaxDynamicSharedMemorySize, FS_SMEM);

    // 1) posenc + operand conversions + cmax init
    pe_kernel<<<(T_ * D_ + 255) / 256, 256>>>(pe);
    addpe2_kernel<<<(B_ * T_ * D_) / 256, 256>>>(queries, pe, q1f, q1h, q1l, k1h, k1l);
    cvt_kernel<<<(D_ * D_ + 255) / 256, 256>>>(W_Q, wqh, wql, D_ * D_);
    cvt_kernel<<<(D_ * D_ + 255) / 256, 256>>>(W_K, wkh, wkl, D_ * D_);
    cvt_kernel<<<(D_ * D_ + 255) / 256, 256>>>(W_V, wvh, nullptr, D_ * D_);
    cvt_kernel<<<(D_ * FF_ + 255) / 256, 256>>>(fw1, f1h, nullptr, D_ * FF_);
    cvt_kernel<<<(FF_ * D_ + 255) / 256, 256>>>(fw2, f2h, nullptr, FF_ * D_);
    initmax_kernel<<<(HB_ * T_ + 255) / 256, 256>>>(cmax, HB_ * T_);

    // 2) Q/K projections (fp16 split) -> hi+lo
    {
        dim3 g(D_ / 128, (B_ * T_) / 128, 1);
        mma4<false, true, 2, false, 2><<<g, 256, SM_SPL0>>>(
            q1h, q1l, 0, 0, D_, wqh, wql, 0, 0, D_,
            nullptr, Qh, Ql, 0, 0, D_, nullptr, 0, 0, 0, nullptr, 1, D_, 1.f, 0);
        mma4<false, true, 2, false, 2><<<g, 256, SM_SPL0>>>(
            k1h, k1l, 0, 0, D_, wkh, wkl, 0, 0, D_,
            nullptr, Kh, Kl, 0, 0, D_, nullptr, 0, 0, 0, nullptr, 1, D_, 1.f, 0);
    }

    // 3) V projection: V = Kp @ W_V (bug kept) -> fp16
    {
        dim3 g(D_ / 128, (B_ * T_) / 128, 1);
        mma4<false, false, 1, false, 3><<<g, 256, SM_PLAIN>>>(
            Kh, nullptr, 0, 0, D_, wvh, nullptr, 0, 0, D_,
            nullptr, Vh, nullptr, 0, 0, D_, nullptr, 0, 0, 0, nullptr, 1, D_, 1.f, 0);
    }

    // 4) scores (fp16 split, B=[N][K]) -> fp32 S + fused column-max atomics
    {
        dim3 g(T_ / 128, T_ / 128, HB_);
        mma4<true, true, 0, true, 2><<<g, 256, SM_SPL1>>>(
            Qh, Ql, DH_, TD, D_,
            Kh, Kl, DH_, TD, D_,
            S, nullptr, nullptr, (long)B_ * TT, TT, T_,
            nullptr, 0, 0, 0, cmax,
            B_, DH_, 0.125f, 0);
    }

    // 5) fused softmax + AV: R = softmax(S - cmax) * qmask @ V + q1
    {
        dim3 g(T_ / 128, HB_);
        fsav_kernel<<<g, 256, FS_SMEM>>>(S, cmax, Vh, q1f, qmasks, R, Rh);
    }

    // 6) FFN1: hidden = relu(R @ fw1) -> fp16
    {
        dim3 g(FF_ / 128, (B_ * T_) / 128, 1);
        mma4<false, false, 1, false, 3><<<g, 256, SM_PLAIN>>>(
            Rh, nullptr, 0, 0, D_, f1h, nullptr, 0, 0, FF_,
            nullptr, Hd, nullptr, 0, 0, FF_, nullptr, 0, 0, 0, nullptr, 1, D_, 1.f, 1);
    }

    // 7) FFN2: out = R + hidden @ fw2 -> fp32
    {
        dim3 g(D_ / 128, (B_ * T_) / 128, 1);
        mma4<false, false, 0, false, 3><<<g, 256, SM_PLAIN>>>(
            Hd, nullptr, 0, 0, FF_, f2h, nullptr, 0, 0, D_,
            out, nullptr, nullptr, 0, 0, D_, R, 0, 0, D_, nullptr, 1, FF_, 1.f, 0);
    }
}